// round 10
// baseline (speedup 1.0000x reference)
#include <cuda_runtime.h>
#include <cuda_bf16.h>
#include <math.h>
#include <stdint.h>

#define DDIM 256
#define PDIM 64
#define MTILE 64
#define NTHREADS 256

// pitches (bytes), ≡16 mod 128 -> conflict-free ldmatrix row sets
#define KQP 144   // split buffers [64][64k] bf16 + 16B pad
#define SP  272   // sims [64 m][64 p] f32 + pad
#define WP  144   // W splits [64 m][64 p] bf16 + pad

// ---- smem offsets ----
#define QH_O 0
#define QM_O 9216
#define QL_O 18432
#define CH_O 27648
#define CM_O 36864
#define CL_O 46080
#define S0_O 0            // sims partials (alias Q/C, dead after GEMM1)
#define S1_O 17408
#define C2_O 0            // GEMM2 C buffers: 2 x (H 9216 + M 9216) = 0..36864
#define C2STRIDE 18432
#define WH_O 36864        // W splits (disjoint from sims and C2 buffers)
#define WL_O 46080
#define QSS_O 55296
#define CISM_O 55552
#define NEGM_O 55808
#define SMEM_BYTES 56064

// ---- precomputed centroid splits ----
__device__ __align__(16) unsigned short gCH[PDIM * DDIM];
__device__ __align__(16) unsigned short gCM[PDIM * DDIM];
__device__ __align__(16) unsigned short gCL[PDIM * DDIM];
__device__ float gCISM[PDIM];
__device__ float gNEGM[PDIM];

__device__ __forceinline__ uint32_t smem_u32(const void* p) {
    uint32_t a;
    asm("{ .reg .u64 t; cvta.to.shared.u64 t, %1; cvt.u32.u64 %0, t; }" : "=r"(a) : "l"(p));
    return a;
}
#define CPA16(dst, src) \
    asm volatile("cp.async.cg.shared.global [%0], [%1], 16;" :: "r"(dst), "l"(src) : "memory")
#define CPA_COMMIT() asm volatile("cp.async.commit_group;" ::: "memory")
#define CPA_WAIT0()  asm volatile("cp.async.wait_group 0;" ::: "memory")
#define CPA_WAIT1()  asm volatile("cp.async.wait_group 1;" ::: "memory")

__device__ __forceinline__ void ldsm4(uint32_t addr, uint32_t& r0, uint32_t& r1,
                                      uint32_t& r2, uint32_t& r3) {
    asm volatile("ldmatrix.sync.aligned.m8n8.x4.shared.b16 {%0,%1,%2,%3}, [%4];"
                 : "=r"(r0), "=r"(r1), "=r"(r2), "=r"(r3) : "r"(addr));
}
__device__ __forceinline__ void ldsm4t(uint32_t addr, uint32_t& r0, uint32_t& r1,
                                       uint32_t& r2, uint32_t& r3) {
    asm volatile("ldmatrix.sync.aligned.m8n8.x4.trans.shared.b16 {%0,%1,%2,%3}, [%4];"
                 : "=r"(r0), "=r"(r1), "=r"(r2), "=r"(r3) : "r"(addr));
}
__device__ __forceinline__ void mma16816(float* d, uint32_t a0, uint32_t a1, uint32_t a2,
                                         uint32_t a3, uint32_t b0, uint32_t b1) {
    asm volatile("mma.sync.aligned.m16n8k16.row.col.f32.bf16.bf16.f32 "
                 "{%0,%1,%2,%3}, {%4,%5,%6,%7}, {%8,%9}, {%0,%1,%2,%3};"
                 : "+f"(d[0]), "+f"(d[1]), "+f"(d[2]), "+f"(d[3])
                 : "r"(a0), "r"(a1), "r"(a2), "r"(a3), "r"(b0), "r"(b1));
}

__device__ __forceinline__ void split3(float x, unsigned short& h, unsigned short& m,
                                       unsigned short& l) {
    __nv_bfloat16 bh = __float2bfloat16(x);
    float r = x - __bfloat162float(bh);
    __nv_bfloat16 bm = __float2bfloat16(r);
    __nv_bfloat16 bl = __float2bfloat16(r - __bfloat162float(bm));
    h = __bfloat16_as_ushort(bh);
    m = __bfloat16_as_ushort(bm);
    l = __bfloat16_as_ushort(bl);
}
__device__ __forceinline__ void split2(float x, unsigned short& h, unsigned short& l) {
    __nv_bfloat16 bh = __float2bfloat16(x);
    __nv_bfloat16 bl = __float2bfloat16(x - __bfloat162float(bh));
    h = __bfloat16_as_ushort(bh);
    l = __bfloat16_as_ushort(bl);
}
__device__ __forceinline__ uint32_t pk(unsigned short a, unsigned short b) {
    return (uint32_t)a | ((uint32_t)b << 16);
}
__device__ __forceinline__ void conv8(const float4* src, char* dh, char* dm, char* dl,
                                      uint32_t off, float& acc) {
    float4 a = src[0], b = src[1];
    float xs[8] = {a.x, a.y, a.z, a.w, b.x, b.y, b.z, b.w};
    unsigned short h[8], m[8], l[8];
    #pragma unroll
    for (int i = 0; i < 8; ++i) {
        acc = fmaf(xs[i], xs[i], acc);
        split3(xs[i], h[i], m[i], l[i]);
    }
    *(uint4*)(dh + off) = make_uint4(pk(h[0], h[1]), pk(h[2], h[3]), pk(h[4], h[5]), pk(h[6], h[7]));
    *(uint4*)(dm + off) = make_uint4(pk(m[0], m[1]), pk(m[2], m[3]), pk(m[4], m[5]), pk(m[6], m[7]));
    *(uint4*)(dl + off) = make_uint4(pk(l[0], l[1]), pk(l[2], l[3]), pk(l[4], l[5]), pk(l[6], l[7]));
}

// ================= prep kernel =================
__global__ void centroid_prep(const float* __restrict__ gc, const int* __restrict__ gmask) {
    const int t = threadIdx.x;           // 256
    const int row = t >> 2, seg = t & 3;
    float acc = 0.f;
    #pragma unroll
    for (int j = 0; j < 8; ++j) {
        const float4* src = (const float4*)(gc + (size_t)row * DDIM + seg * 64 + j * 8);
        float4 a = src[0], b = src[1];
        float xs[8] = {a.x, a.y, a.z, a.w, b.x, b.y, b.z, b.w};
        unsigned short h[8], m[8], l[8];
        #pragma unroll
        for (int i = 0; i < 8; ++i) {
            acc = fmaf(xs[i], xs[i], acc);
            split3(xs[i], h[i], m[i], l[i]);
        }
        const int idx = row * DDIM + seg * 64 + j * 8;
        *(uint4*)(gCH + idx) = make_uint4(pk(h[0], h[1]), pk(h[2], h[3]), pk(h[4], h[5]), pk(h[6], h[7]));
        *(uint4*)(gCM + idx) = make_uint4(pk(m[0], m[1]), pk(m[2], m[3]), pk(m[4], m[5]), pk(m[6], m[7]));
        *(uint4*)(gCL + idx) = make_uint4(pk(l[0], l[1]), pk(l[2], l[3]), pk(l[4], l[5]), pk(l[6], l[7]));
    }
    acc += __shfl_xor_sync(0xffffffffu, acc, 1);
    acc += __shfl_xor_sync(0xffffffffu, acc, 2);
    if (seg == 0) {
        int mk = gmask[row];
        gCISM[row] = mk ? rsqrtf(fmaxf(acc, 1e-24f)) : 0.f;
        gNEGM[row] = mk ? 0.f : -1e9f;
    }
}

// cp.async one k-quarter (128B/row) of a precomputed split into pitched smem
__device__ __forceinline__ void copy_cq(uint32_t dstbase, const unsigned short* gsrc,
                                        int row, int seg, int kq) {
    uint32_t dst = dstbase + (uint32_t)(row * KQP + seg * 32);
    uint64_t src = __cvta_generic_to_global(gsrc + row * DDIM + kq * 64 + seg * 16);
    CPA16(dst, src);
    CPA16(dst + 16, src + 16);
}

__global__ void __launch_bounds__(NTHREADS, 4)
centroid_main(const float* __restrict__ gq,
              float* __restrict__ gctx,
              float* __restrict__ gw,
              float* __restrict__ ghard)
{
    extern __shared__ char sm[];
    const uint32_t smb = smem_u32(sm);
    const int t = threadIdx.x;
    const int wid = t >> 5, lane = t & 31;
    const int mbase = blockIdx.x * MTILE;

    float* qssf = (float*)(sm + QSS_O);
    float* cism = (float*)(sm + CISM_O);
    float* negm = (float*)(sm + NEGM_O);

    const int g = wid >> 2;
    const int mrow = ((wid >> 1) & 1) * 32;
    const int ncol = (wid & 1) * 32;
    const int row4 = t >> 2, seg4 = t & 3;

    if (t < 64) {
        cism[t] = gCISM[t];
        negm[t] = gNEGM[t];
    }

    float qacc = 0.f;
    float acc[8][4];
    #pragma unroll
    for (int i = 0; i < 8; ++i)
        #pragma unroll
        for (int j = 0; j < 4; ++j) acc[i][j] = 0.f;

    const uint32_t lrow = (uint32_t)(lane & 15);
    const uint32_t lk = (uint32_t)((lane >> 4) * 16);

    // ================= GEMM1 over four K-quarters =================
    #pragma unroll 1
    for (int kq = 0; kq < 4; ++kq) {
        copy_cq(smb + CH_O, gCH, row4, seg4, kq);
        copy_cq(smb + CM_O, gCM, row4, seg4, kq);
        copy_cq(smb + CL_O, gCL, row4, seg4, kq);
        CPA_COMMIT();
        // convert Q k-quarter [64][64] (16 elems/thread), overlaps cp.async
        {
            const float4* src = (const float4*)(gq + (size_t)(mbase + row4) * DDIM + kq * 64 + seg4 * 16);
            uint32_t base = (uint32_t)(row4 * KQP + seg4 * 32);
            conv8(src,     sm + QH_O, sm + QM_O, sm + QL_O, base,      qacc);
            conv8(src + 2, sm + QH_O, sm + QM_O, sm + QL_O, base + 16, qacc);
        }
        if (kq == 3) {
            qacc += __shfl_xor_sync(0xffffffffu, qacc, 1);
            qacc += __shfl_xor_sync(0xffffffffu, qacc, 2);
            if (seg4 == 0) qssf[row4] = qacc;
        }
        CPA_WAIT0();
        __syncthreads();
        {
            const uint32_t qofs[6] = {QH_O, QH_O, QM_O, QH_O, QL_O, QM_O};
            const uint32_t cofs[6] = {CH_O, CM_O, CH_O, CL_O, CH_O, CM_O};
            #pragma unroll 1
            for (int ps = 0; ps < 3; ++ps) {
                uint32_t ab = smb + qofs[g * 3 + ps] + (mrow + lrow) * KQP + lk;
                uint32_t bb = smb + cofs[g * 3 + ps] + (ncol + lrow) * KQP + lk;
                uint32_t bb2 = bb + 16 * KQP;
                #pragma unroll
                for (int ks = 0; ks < 4; ++ks) {
                    uint32_t a0, a1, a2, a3, a4, a5, a6, a7, e0, e1, e2, e3, f0, f1, f2, f3;
                    ldsm4(ab + ks * 32, a0, a1, a2, a3);
                    ldsm4(ab + 16 * KQP + ks * 32, a4, a5, a6, a7);
                    ldsm4(bb + ks * 32, e0, e1, e2, e3);
                    ldsm4(bb2 + ks * 32, f0, f1, f2, f3);
                    mma16816(acc[0], a0, a1, a2, a3, e0, e2);
                    mma16816(acc[1], a0, a1, a2, a3, e1, e3);
                    mma16816(acc[2], a0, a1, a2, a3, f0, f2);
                    mma16816(acc[3], a0, a1, a2, a3, f1, f3);
                    mma16816(acc[4], a4, a5, a6, a7, e0, e2);
                    mma16816(acc[5], a4, a5, a6, a7, e1, e3);
                    mma16816(acc[6], a4, a5, a6, a7, f0, f2);
                    mma16816(acc[7], a4, a5, a6, a7, f1, f3);
                }
            }
        }
        __syncthreads();
    }

    // ---- store partial sims ----
    {
        char* sbase = sm + (g ? S1_O : S0_O);
        const int r0 = mrow + (lane >> 2);
        const int cb = ncol + (lane & 3) * 2;
        #pragma unroll
        for (int mf = 0; mf < 2; ++mf)
            #pragma unroll
            for (int nf = 0; nf < 4; ++nf) {
                float* a = acc[mf * 4 + nf];
                *(float2*)(sbase + (r0 + mf * 16) * SP + (cb + nf * 8) * 4) = make_float2(a[0], a[1]);
                *(float2*)(sbase + (r0 + mf * 16 + 8) * SP + (cb + nf * 8) * 4) = make_float2(a[2], a[3]);
            }
    }
    __syncthreads();

    // ================= softmax + argmax: 4 threads per row =================
    {
        const int m = t >> 2, part = t & 3;
        const float qr = rsqrtf(fmaxf(qssf[m], 1e-24f));
        const float4* s0 = (const float4*)(sm + S0_O + m * SP) + part * 4;
        const float4* s1 = (const float4*)(sm + S1_O + m * SP) + part * 4;
        float s[16];
        float mx = -INFINITY;
        int mi = PDIM;
        #pragma unroll
        for (int gg = 0; gg < 4; ++gg) {
            float4 v = s0[gg], u = s1[gg];
            float vv[4] = {v.x + u.x, v.y + u.y, v.z + u.z, v.w + u.w};
            #pragma unroll
            for (int i = 0; i < 4; ++i) {
                int p = part * 16 + gg * 4 + i;
                float val = fmaf(vv[i] * qr, cism[p], negm[p]);
                s[gg * 4 + i] = val;
                if (val > mx) { mx = val; mi = p; }     // strict >: first index wins
            }
        }
        #pragma unroll
        for (int off = 1; off < 4; off <<= 1) {
            float omx = __shfl_xor_sync(0xffffffffu, mx, off);
            int   omi = __shfl_xor_sync(0xffffffffu, mi, off);
            if (omx > mx || (omx == mx && omi < mi)) { mx = omx; mi = omi; }
        }
        float ssum = 0.f;
        #pragma unroll
        for (int i = 0; i < 16; ++i) {
            float e = expf(s[i] - mx);
            s[i] = e;
            ssum += e;
        }
        #pragma unroll
        for (int off = 1; off < 4; off <<= 1)
            ssum += __shfl_xor_sync(0xffffffffu, ssum, off);
        const float inv = 1.0f / ssum;

        // W region (36864+) is disjoint from sims (0..34816): write directly
        float4* gwp = (float4*)(gw + (size_t)(mbase + m) * PDIM + part * 16);
        char* wh = sm + WH_O + m * WP + part * 32;
        char* wl = sm + WL_O + m * WP + part * 32;
        #pragma unroll
        for (int gg = 0; gg < 4; ++gg) {
            float w0 = s[4 * gg + 0] * inv, w1 = s[4 * gg + 1] * inv;
            float w2 = s[4 * gg + 2] * inv, w3 = s[4 * gg + 3] * inv;
            gwp[gg] = make_float4(w0, w1, w2, w3);
            unsigned short h0, l0, h1, l1, h2, l2, h3, l3;
            split2(w0, h0, l0); split2(w1, h1, l1);
            split2(w2, h2, l2); split2(w3, h3, l3);
            *(uint2*)(wh + gg * 8) = make_uint2(pk(h0, h1), pk(h2, h3));
            *(uint2*)(wl + gg * 8) = make_uint2(pk(l0, l1), pk(l2, l3));
        }
        if (part == 0) ghard[mbase + m] = (float)mi;
    }
    __syncthreads();

    // ================= GEMM2: 4 d-quarter rounds, double-buffered =================
    {
        const int mrow2 = (wid & 1) * 32;
        const int dt = (wid >> 1) * 16;
        const uint32_t btrow = (uint32_t)((lane >> 4) * 8 + (lane & 7));
        const uint32_t btcol = (uint32_t)(((lane >> 3) & 1) * 16);
        const uint32_t wofs[3] = {WH_O, WH_O, WL_O};

        // prologue: prefetch quarter 0 into buffer 0
        copy_cq(smb + C2_O, gCH, row4, seg4, 0);
        copy_cq(smb + C2_O + 9216, gCM, row4, seg4, 0);
        CPA_COMMIT();

        #pragma unroll 1
        for (int dq = 0; dq < 4; ++dq) {
            const uint32_t cbuf = C2_O + (uint32_t)(dq & 1) * C2STRIDE;
            if (dq < 3) {
                const uint32_t nbuf = C2_O + (uint32_t)((dq + 1) & 1) * C2STRIDE;
                copy_cq(smb + nbuf, gCH, row4, seg4, dq + 1);
                copy_cq(smb + nbuf + 9216, gCM, row4, seg4, dq + 1);
                CPA_COMMIT();
                CPA_WAIT1();
            } else {
                CPA_WAIT0();
            }
            __syncthreads();

            float dd[4][4];
            #pragma unroll
            for (int i = 0; i < 4; ++i)
                #pragma unroll
                for (int j = 0; j < 4; ++j) dd[i][j] = 0.f;

            const uint32_t cofs2[3] = {cbuf, cbuf + 9216, cbuf};   // C mid == split2-lo of C
            #pragma unroll 1
            for (int ps = 0; ps < 3; ++ps) {
                uint32_t ab = smb + wofs[ps] + (mrow2 + lrow) * WP + lk;
                uint32_t bb = smb + cofs2[ps] + btrow * KQP + dt * 2 + btcol;
                #pragma unroll
                for (int ks = 0; ks < 4; ++ks) {
                    uint32_t a0, a1, a2, a3, a4, a5, a6, a7, r0, r1, r2, r3;
                    ldsm4(ab + ks * 32, a0, a1, a2, a3);
                    ldsm4(ab + 16 * WP + ks * 32, a4, a5, a6, a7);
                    ldsm4t(bb + ks * 16 * KQP, r0, r1, r2, r3);
                    mma16816(dd[0], a0, a1, a2, a3, r0, r2);
                    mma16816(dd[1], a0, a1, a2, a3, r1, r3);
                    mma16816(dd[2], a4, a5, a6, a7, r0, r2);
                    mma16816(dd[3], a4, a5, a6, a7, r1, r3);
                }
            }
            // store this d-quarter slice
            const int r0l = lane >> 2;
            const int cb = dq * 64 + dt + (lane & 3) * 2;
            #pragma unroll
            for (int mf = 0; mf < 2; ++mf) {
                float* gr0 = gctx + (size_t)(mbase + mrow2 + mf * 16 + r0l) * DDIM;
                float* gr1 = gr0 + 8 * DDIM;
                #pragma unroll
                for (int nf = 0; nf < 2; ++nf) {
                    float* a = dd[mf * 2 + nf];
                    *(float2*)(gr0 + cb + nf * 8) = make_float2(a[0], a[1]);
                    *(float2*)(gr1 + cb + nf * 8) = make_float2(a[2], a[3]);
                }
            }
            __syncthreads();   // reads done before next round's prefetch overwrites
        }
    }
}

extern "C" void kernel_launch(void* const* d_in, const int* in_sizes, int n_in,
                              void* d_out, int out_size)
{
    const float* q = (const float*)d_in[0];
    const float* c = (const float*)d_in[1];
    const int*   mask = (const int*)d_in[2];

    const int Pn = in_sizes[2];              // 64
    const int Dn = in_sizes[1] / Pn;         // 256
    const int B  = in_sizes[0] / Dn;         // 131072

    float* out  = (float*)d_out;
    float* ctx  = out;                           // [B, D]
    float* w    = out + (size_t)B * Dn;          // [B, P]
    float* hard = w + (size_t)B * Pn;            // [B]

    centroid_prep<<<1, 256>>>(c, mask);
    cudaFuncSetAttribute(centroid_main,
                         cudaFuncAttributeMaxDynamicSharedMemorySize, SMEM_BYTES);
    centroid_main<<<B / MTILE, NTHREADS, SMEM_BYTES>>>(q, ctx, w, hard);
}

// round 11
// speedup vs baseline: 1.1752x; 1.1752x over previous
#include <cuda_runtime.h>
#include <cuda_bf16.h>
#include <math.h>
#include <stdint.h>

#define DDIM 256
#define PDIM 64
#define MTILE 64
#define NTHREADS 256

#define KQP 144   // split buffers [64][64k] bf16 + 16B pad
#define SP  272   // sims [64 m][64 p] f32 + pad
#define WP  144   // W splits [64 m][64 p] bf16 + pad

// ---- smem offsets ----
#define QH_O 0
#define QM_O 9216
#define QL_O 18432
#define CH_O 27648
#define CM_O 36864
#define CL_O 46080
#define S0_O 0
#define S1_O 17408
#define C2_O 0
#define C2STRIDE 18432
#define WH_O 36864
#define WL_O 46080
#define QSS_O 55296
#define CISM_O 55552
#define NEGM_O 55808
#define SMEM_BYTES 56064

__device__ __align__(16) unsigned short gCH[PDIM * DDIM];
__device__ __align__(16) unsigned short gCM[PDIM * DDIM];
__device__ __align__(16) unsigned short gCL[PDIM * DDIM];
__device__ float gCISM[PDIM];
__device__ float gNEGM[PDIM];

__device__ __forceinline__ uint32_t smem_u32(const void* p) {
    uint32_t a;
    asm("{ .reg .u64 t; cvta.to.shared.u64 t, %1; cvt.u32.u64 %0, t; }" : "=r"(a) : "l"(p));
    return a;
}
#define CPA16(dst, src) \
    asm volatile("cp.async.cg.shared.global [%0], [%1], 16;" :: "r"(dst), "l"(src) : "memory")
#define CPA_COMMIT() asm volatile("cp.async.commit_group;" ::: "memory")
#define CPA_WAIT0()  asm volatile("cp.async.wait_group 0;" ::: "memory")
#define CPA_WAIT1()  asm volatile("cp.async.wait_group 1;" ::: "memory")

__device__ __forceinline__ void ldsm4(uint32_t addr, uint32_t& r0, uint32_t& r1,
                                      uint32_t& r2, uint32_t& r3) {
    asm volatile("ldmatrix.sync.aligned.m8n8.x4.shared.b16 {%0,%1,%2,%3}, [%4];"
                 : "=r"(r0), "=r"(r1), "=r"(r2), "=r"(r3) : "r"(addr));
}
__device__ __forceinline__ void ldsm4t(uint32_t addr, uint32_t& r0, uint32_t& r1,
                                       uint32_t& r2, uint32_t& r3) {
    asm volatile("ldmatrix.sync.aligned.m8n8.x4.trans.shared.b16 {%0,%1,%2,%3}, [%4];"
                 : "=r"(r0), "=r"(r1), "=r"(r2), "=r"(r3) : "r"(addr));
}
__device__ __forceinline__ void mma16816(float* d, uint32_t a0, uint32_t a1, uint32_t a2,
                                         uint32_t a3, uint32_t b0, uint32_t b1) {
    asm volatile("mma.sync.aligned.m16n8k16.row.col.f32.bf16.bf16.f32 "
                 "{%0,%1,%2,%3}, {%4,%5,%6,%7}, {%8,%9}, {%0,%1,%2,%3};"
                 : "+f"(d[0]), "+f"(d[1]), "+f"(d[2]), "+f"(d[3])
                 : "r"(a0), "r"(a1), "r"(a2), "r"(a3), "r"(b0), "r"(b1));
}
// 8 MMAs: A (a0..a7 = 32 rows) x B (e = cols 0-15, f = cols 16-31)
#define MMA8(acc, a0,a1,a2,a3,a4,a5,a6,a7, e0,e1,e2,e3, f0,f1,f2,f3) do { \
    mma16816((acc)[0], a0,a1,a2,a3, e0,e2); \
    mma16816((acc)[1], a0,a1,a2,a3, e1,e3); \
    mma16816((acc)[2], a0,a1,a2,a3, f0,f2); \
    mma16816((acc)[3], a0,a1,a2,a3, f1,f3); \
    mma16816((acc)[4], a4,a5,a6,a7, e0,e2); \
    mma16816((acc)[5], a4,a5,a6,a7, e1,e3); \
    mma16816((acc)[6], a4,a5,a6,a7, f0,f2); \
    mma16816((acc)[7], a4,a5,a6,a7, f1,f3); \
} while (0)

// packed bf16x2 convert: x1 -> high half, x0 -> low half (cvt.rn, same as __float2bfloat16)
__device__ __forceinline__ uint32_t cvt2(float x1, float x0) {
    uint32_t r;
    asm("cvt.rn.bf16x2.f32 %0, %1, %2;" : "=r"(r) : "f"(x1), "f"(x0));
    return r;
}
__device__ __forceinline__ float fhi(uint32_t p) { return __uint_as_float(p & 0xFFFF0000u); }
__device__ __forceinline__ float flo(uint32_t p) { return __uint_as_float(p << 16); }

__device__ __forceinline__ void split3(float x, unsigned short& h, unsigned short& m,
                                       unsigned short& l) {
    __nv_bfloat16 bh = __float2bfloat16(x);
    float r = x - __bfloat162float(bh);
    __nv_bfloat16 bm = __float2bfloat16(r);
    __nv_bfloat16 bl = __float2bfloat16(r - __bfloat162float(bm));
    h = __bfloat16_as_ushort(bh);
    m = __bfloat16_as_ushort(bm);
    l = __bfloat16_as_ushort(bl);
}
__device__ __forceinline__ uint32_t pk(unsigned short a, unsigned short b) {
    return (uint32_t)a | ((uint32_t)b << 16);
}

// 8 fp32 -> 16B per split buffer using packed cvt; accumulate sumsq
__device__ __forceinline__ void conv8p(const float4* src, char* dh, char* dm, char* dl,
                                       uint32_t off, float& acc) {
    float4 a = src[0], b = src[1];
    float xs[8] = {a.x, a.y, a.z, a.w, b.x, b.y, b.z, b.w};
    uint32_t H[4], M[4], L[4];
    #pragma unroll
    for (int i = 0; i < 4; ++i) {
        float x0 = xs[2 * i], x1 = xs[2 * i + 1];
        acc = fmaf(x0, x0, acc);
        acc = fmaf(x1, x1, acc);
        uint32_t h = cvt2(x1, x0);
        float r0 = x0 - flo(h), r1 = x1 - fhi(h);
        uint32_t m = cvt2(r1, r0);
        float s0 = r0 - flo(m), s1 = r1 - fhi(m);
        H[i] = h;
        M[i] = m;
        L[i] = cvt2(s1, s0);
    }
    *(uint4*)(dh + off) = make_uint4(H[0], H[1], H[2], H[3]);
    *(uint4*)(dm + off) = make_uint4(M[0], M[1], M[2], M[3]);
    *(uint4*)(dl + off) = make_uint4(L[0], L[1], L[2], L[3]);
}

// ================= prep kernel =================
__global__ void centroid_prep(const float* __restrict__ gc, const int* __restrict__ gmask) {
    const int t = threadIdx.x;           // 256
    const int row = t >> 2, seg = t & 3;
    float acc = 0.f;
    #pragma unroll
    for (int j = 0; j < 8; ++j) {
        const float4* src = (const float4*)(gc + (size_t)row * DDIM + seg * 64 + j * 8);
        float4 a = src[0], b = src[1];
        float xs[8] = {a.x, a.y, a.z, a.w, b.x, b.y, b.z, b.w};
        unsigned short h[8], m[8], l[8];
        #pragma unroll
        for (int i = 0; i < 8; ++i) {
            acc = fmaf(xs[i], xs[i], acc);
            split3(xs[i], h[i], m[i], l[i]);
        }
        const int idx = row * DDIM + seg * 64 + j * 8;
        *(uint4*)(gCH + idx) = make_uint4(pk(h[0], h[1]), pk(h[2], h[3]), pk(h[4], h[5]), pk(h[6], h[7]));
        *(uint4*)(gCM + idx) = make_uint4(pk(m[0], m[1]), pk(m[2], m[3]), pk(m[4], m[5]), pk(m[6], m[7]));
        *(uint4*)(gCL + idx) = make_uint4(pk(l[0], l[1]), pk(l[2], l[3]), pk(l[4], l[5]), pk(l[6], l[7]));
    }
    acc += __shfl_xor_sync(0xffffffffu, acc, 1);
    acc += __shfl_xor_sync(0xffffffffu, acc, 2);
    if (seg == 0) {
        int mk = gmask[row];
        gCISM[row] = mk ? rsqrtf(fmaxf(acc, 1e-24f)) : 0.f;
        gNEGM[row] = mk ? 0.f : -1e9f;
    }
}

__device__ __forceinline__ void copy_cq(uint32_t dstbase, const unsigned short* gsrc,
                                        int row, int seg, int kq) {
    uint32_t dst = dstbase + (uint32_t)(row * KQP + seg * 32);
    uint64_t src = __cvta_generic_to_global(gsrc + row * DDIM + kq * 64 + seg * 16);
    CPA16(dst, src);
    CPA16(dst + 16, src + 16);
}

__global__ void __launch_bounds__(NTHREADS, 3)
centroid_main(const float* __restrict__ gq,
              float* __restrict__ gctx,
              float* __restrict__ gw,
              float* __restrict__ ghard)
{
    extern __shared__ char sm[];
    const uint32_t smb = smem_u32(sm);
    const int t = threadIdx.x;
    const int wid = t >> 5, lane = t & 31;
    const int mbase = blockIdx.x * MTILE;

    float* qssf = (float*)(sm + QSS_O);
    float* cism = (float*)(sm + CISM_O);
    float* negm = (float*)(sm + NEGM_O);

    const int g = wid >> 2;
    const int mrow = ((wid >> 1) & 1) * 32;
    const int ncol = (wid & 1) * 32;
    const int row4 = t >> 2, seg4 = t & 3;

    if (t < 64) {
        cism[t] = gCISM[t];
        negm[t] = gNEGM[t];
    }

    float qacc = 0.f;
    float acc[8][4];
    #pragma unroll
    for (int i = 0; i < 8; ++i)
        #pragma unroll
        for (int j = 0; j < 4; ++j) acc[i][j] = 0.f;

    const uint32_t lrow = (uint32_t)(lane & 15);
    const uint32_t lk = (uint32_t)((lane >> 4) * 16);

    // ================= GEMM1 over four K-quarters =================
    #pragma unroll 1
    for (int kq = 0; kq < 4; ++kq) {
        copy_cq(smb + CH_O, gCH, row4, seg4, kq);
        copy_cq(smb + CM_O, gCM, row4, seg4, kq);
        copy_cq(smb + CL_O, gCL, row4, seg4, kq);
        CPA_COMMIT();
        {
            const float4* src = (const float4*)(gq + (size_t)(mbase + row4) * DDIM + kq * 64 + seg4 * 16);
            uint32_t base = (uint32_t)(row4 * KQP + seg4 * 32);
            conv8p(src,     sm + QH_O, sm + QM_O, sm + QL_O, base,      qacc);
            conv8p(src + 2, sm + QH_O, sm + QM_O, sm + QL_O, base + 16, qacc);
        }
        if (kq == 3) {
            qacc += __shfl_xor_sync(0xffffffffu, qacc, 1);
            qacc += __shfl_xor_sync(0xffffffffu, qacc, 2);
            if (seg4 == 0) qssf[row4] = qacc;
        }
        CPA_WAIT0();
        __syncthreads();

        // ---- fully unrolled, A/B-fragment-sharing MMA schedule ----
        const uint32_t arow = (mrow + lrow) * KQP + lk;
        const uint32_t brow = (ncol + lrow) * KQP + lk;
        if (g == 0) {
            // passes: QH x {CH, CM, CL}; A loaded once per ks
            const uint32_t aQH = smb + QH_O + arow;
            const uint32_t bCH = smb + CH_O + brow;
            const uint32_t bCM = smb + CM_O + brow;
            const uint32_t bCL = smb + CL_O + brow;
            #pragma unroll
            for (int ks = 0; ks < 4; ++ks) {
                uint32_t a0, a1, a2, a3, a4, a5, a6, a7;
                ldsm4(aQH + ks * 32, a0, a1, a2, a3);
                ldsm4(aQH + 16 * KQP + ks * 32, a4, a5, a6, a7);
                uint32_t e0, e1, e2, e3, f0, f1, f2, f3;
                ldsm4(bCH + ks * 32, e0, e1, e2, e3);
                ldsm4(bCH + 16 * KQP + ks * 32, f0, f1, f2, f3);
                MMA8(acc, a0,a1,a2,a3,a4,a5,a6,a7, e0,e1,e2,e3, f0,f1,f2,f3);
                ldsm4(bCM + ks * 32, e0, e1, e2, e3);
                ldsm4(bCM + 16 * KQP + ks * 32, f0, f1, f2, f3);
                MMA8(acc, a0,a1,a2,a3,a4,a5,a6,a7, e0,e1,e2,e3, f0,f1,f2,f3);
                ldsm4(bCL + ks * 32, e0, e1, e2, e3);
                ldsm4(bCL + 16 * KQP + ks * 32, f0, f1, f2, f3);
                MMA8(acc, a0,a1,a2,a3,a4,a5,a6,a7, e0,e1,e2,e3, f0,f1,f2,f3);
            }
        } else {
            // passes: QM x {CH, CM} (A shared), QL x CH (B held)
            const uint32_t aQM = smb + QM_O + arow;
            const uint32_t aQL = smb + QL_O + arow;
            const uint32_t bCH = smb + CH_O + brow;
            const uint32_t bCM = smb + CM_O + brow;
            #pragma unroll
            for (int ks = 0; ks < 4; ++ks) {
                uint32_t a0, a1, a2, a3, a4, a5, a6, a7;
                uint32_t e0, e1, e2, e3, f0, f1, f2, f3;   // CH frags, held
                uint32_t u0, u1, u2, u3, v0, v1, v2, v3;   // CM frags
                ldsm4(aQM + ks * 32, a0, a1, a2, a3);
                ldsm4(aQM + 16 * KQP + ks * 32, a4, a5, a6, a7);
                ldsm4(bCH + ks * 32, e0, e1, e2, e3);
                ldsm4(bCH + 16 * KQP + ks * 32, f0, f1, f2, f3);
                MMA8(acc, a0,a1,a2,a3,a4,a5,a6,a7, e0,e1,e2,e3, f0,f1,f2,f3);
                ldsm4(bCM + ks * 32, u0, u1, u2, u3);
                ldsm4(bCM + 16 * KQP + ks * 32, v0, v1, v2, v3);
                MMA8(acc, a0,a1,a2,a3,a4,a5,a6,a7, u0,u1,u2,u3, v0,v1,v2,v3);
                ldsm4(aQL + ks * 32, a0, a1, a2, a3);
                ldsm4(aQL + 16 * KQP + ks * 32, a4, a5, a6, a7);
                MMA8(acc, a0,a1,a2,a3,a4,a5,a6,a7, e0,e1,e2,e3, f0,f1,f2,f3);
            }
        }
        __syncthreads();
    }

    // ---- store partial sims ----
    {
        char* sbase = sm + (g ? S1_O : S0_O);
        const int r0 = mrow + (lane >> 2);
        const int cb = ncol + (lane & 3) * 2;
        #pragma unroll
        for (int mf = 0; mf < 2; ++mf)
            #pragma unroll
            for (int nf = 0; nf < 4; ++nf) {
                float* a = acc[mf * 4 + nf];
                *(float2*)(sbase + (r0 + mf * 16) * SP + (cb + nf * 8) * 4) = make_float2(a[0], a[1]);
                *(float2*)(sbase + (r0 + mf * 16 + 8) * SP + (cb + nf * 8) * 4) = make_float2(a[2], a[3]);
            }
    }
    __syncthreads();

    // ================= softmax + argmax: 4 threads per row =================
    {
        const int m = t >> 2, part = t & 3;
        const float qr = rsqrtf(fmaxf(qssf[m], 1e-24f));
        const float4* s0 = (const float4*)(sm + S0_O + m * SP) + part * 4;
        const float4* s1 = (const float4*)(sm + S1_O + m * SP) + part * 4;
        float s[16];
        float mx = -INFINITY;
        int mi = PDIM;
        #pragma unroll
        for (int gg = 0; gg < 4; ++gg) {
            float4 v = s0[gg], u = s1[gg];
            float vv[4] = {v.x + u.x, v.y + u.y, v.z + u.z, v.w + u.w};
            #pragma unroll
            for (int i = 0; i < 4; ++i) {
                int p = part * 16 + gg * 4 + i;
                float val = fmaf(vv[i] * qr, cism[p], negm[p]);
                s[gg * 4 + i] = val;
                if (val > mx) { mx = val; mi = p; }     // strict >: first index wins
            }
        }
        #pragma unroll
        for (int off = 1; off < 4; off <<= 1) {
            float omx = __shfl_xor_sync(0xffffffffu, mx, off);
            int   omi = __shfl_xor_sync(0xffffffffu, mi, off);
            if (omx > mx || (omx == mx && omi < mi)) { mx = omx; mi = omi; }
        }
        float ssum = 0.f;
        #pragma unroll
        for (int i = 0; i < 16; ++i) {
            float e = expf(s[i] - mx);
            s[i] = e;
            ssum += e;
        }
        #pragma unroll
        for (int off = 1; off < 4; off <<= 1)
            ssum += __shfl_xor_sync(0xffffffffu, ssum, off);
        const float inv = 1.0f / ssum;

        float4* gwp = (float4*)(gw + (size_t)(mbase + m) * PDIM + part * 16);
        char* wh = sm + WH_O + m * WP + part * 32;
        char* wl = sm + WL_O + m * WP + part * 32;
        #pragma unroll
        for (int gg = 0; gg < 2; ++gg) {
            float w0 = s[8 * gg + 0] * inv, w1 = s[8 * gg + 1] * inv;
            float w2 = s[8 * gg + 2] * inv, w3 = s[8 * gg + 3] * inv;
            float w4 = s[8 * gg + 4] * inv, w5 = s[8 * gg + 5] * inv;
            float w6 = s[8 * gg + 6] * inv, w7 = s[8 * gg + 7] * inv;
            gwp[2 * gg]     = make_float4(w0, w1, w2, w3);
            gwp[2 * gg + 1] = make_float4(w4, w5, w6, w7);
            uint32_t h0 = cvt2(w1, w0), h1 = cvt2(w3, w2);
            uint32_t h2 = cvt2(w5, w4), h3 = cvt2(w7, w6);
            uint32_t l0 = cvt2(w1 - fhi(h0), w0 - flo(h0));
            uint32_t l1 = cvt2(w3 - fhi(h1), w2 - flo(h1));
            uint32_t l2 = cvt2(w5 - fhi(h2), w4 - flo(h2));
            uint32_t l3 = cvt2(w7 - fhi(h3), w6 - flo(h3));
            *(uint4*)(wh + gg * 16) = make_uint4(h0, h1, h2, h3);
            *(uint4*)(wl + gg * 16) = make_uint4(l0, l1, l2, l3);
        }
        if (part == 0) ghard[mbase + m] = (float)mi;
    }
    __syncthreads();

    // ================= GEMM2: 4 d-quarter rounds, double-buffered =================
    {
        const int mrow2 = (wid & 1) * 32;
        const int dt = (wid >> 1) * 16;
        const uint32_t btrow = (uint32_t)((lane >> 4) * 8 + (lane & 7));
        const uint32_t btcol = (uint32_t)(((lane >> 3) & 1) * 16);
        const uint32_t aWHr = smb + WH_O + (mrow2 + lrow) * WP + lk;
        const uint32_t aWLr = smb + WL_O + (mrow2 + lrow) * WP + lk;

        copy_cq(smb + C2_O, gCH, row4, seg4, 0);
        copy_cq(smb + C2_O + 9216, gCM, row4, seg4, 0);
        CPA_COMMIT();

        #pragma unroll 1
        for (int dq = 0; dq < 4; ++dq) {
            const uint32_t cbuf = C2_O + (uint32_t)(dq & 1) * C2STRIDE;
            if (dq < 3) {
                const uint32_t nbuf = C2_O + (uint32_t)((dq + 1) & 1) * C2STRIDE;
                copy_cq(smb + nbuf, gCH, row4, seg4, dq + 1);
                copy_cq(smb + nbuf + 9216, gCM, row4, seg4, dq + 1);
                CPA_COMMIT();
                CPA_WAIT1();
            } else {
                CPA_WAIT0();
            }
            __syncthreads();

            float dd[4][4];
            #pragma unroll
            for (int i = 0; i < 4; ++i)
                #pragma unroll
                for (int j = 0; j < 4; ++j) dd[i][j] = 0.f;

            const uint32_t bC2H = smb + cbuf + btrow * KQP + dt * 2 + btcol;
            const uint32_t bC2M = bC2H + 9216;
            #pragma unroll
            for (int ks = 0; ks < 4; ++ks) {
                uint32_t a0, a1, a2, a3, a4, a5, a6, a7;
                uint32_t r0, r1, r2, r3, s0, s1, s2, s3;
                ldsm4(aWHr + ks * 32, a0, a1, a2, a3);
                ldsm4(aWHr + 16 * WP + ks * 32, a4, a5, a6, a7);
                ldsm4t(bC2H + ks * 16 * KQP, r0, r1, r2, r3);   // CH frags, held
                mma16816(dd[0], a0, a1, a2, a3, r0, r2);
                mma16816(dd[1], a0, a1, a2, a3, r1, r3);
                mma16816(dd[2], a4, a5, a6, a7, r0, r2);
                mma16816(dd[3], a4, a5, a6, a7, r1, r3);
                ldsm4t(bC2M + ks * 16 * KQP, s0, s1, s2, s3);
                mma16816(dd[0], a0, a1, a2, a3, s0, s2);
                mma16816(dd[1], a0, a1, a2, a3, s1, s3);
                mma16816(dd[2], a4, a5, a6, a7, s0, s2);
                mma16816(dd[3], a4, a5, a6, a7, s1, s3);
                ldsm4(aWLr + ks * 32, a0, a1, a2, a3);
                ldsm4(aWLr + 16 * WP + ks * 32, a4, a5, a6, a7);
                mma16816(dd[0], a0, a1, a2, a3, r0, r2);
                mma16816(dd[1], a0, a1, a2, a3, r1, r3);
                mma16816(dd[2], a4, a5, a6, a7, r0, r2);
                mma16816(dd[3], a4, a5, a6, a7, r1, r3);
            }
            const int r0l = lane >> 2;
            const int cb = dq * 64 + dt + (lane & 3) * 2;
            #pragma unroll
            for (int mf = 0; mf < 2; ++mf) {
                float* gr0 = gctx + (size_t)(mbase + mrow2 + mf * 16 + r0l) * DDIM;
                float* gr1 = gr0 + 8 * DDIM;
                #pragma unroll
                for (int nf = 0; nf < 2; ++nf) {
                    float* a = dd[mf * 2 + nf];
                    *(float2*)(gr0 + cb + nf * 8) = make_float2(a[0], a[1]);
                    *(float2*)(gr1 + cb + nf * 8) = make_float2(a[2], a[3]);
                }
            }
            __syncthreads();
        }
    }
}

extern "C" void kernel_launch(void* const* d_in, const int* in_sizes, int n_in,
                              void* d_out, int out_size)
{
    const float* q = (const float*)d_in[0];
    const float* c = (const float*)d_in[1];
    const int*   mask = (const int*)d_in[2];

    const int Pn = in_sizes[2];              // 64
    const int Dn = in_sizes[1] / Pn;         // 256
    const int B  = in_sizes[0] / Dn;         // 131072

    float* out  = (float*)d_out;
    float* ctx  = out;                           // [B, D]
    float* w    = out + (size_t)B * Dn;          // [B, P]
    float* hard = w + (size_t)B * Pn;            // [B]

    centroid_prep<<<1, 256>>>(c, mask);
    cudaFuncSetAttribute(centroid_main,
                         cudaFuncAttributeMaxDynamicSharedMemorySize, SMEM_BYTES);
    centroid_main<<<B / MTILE, NTHREADS, SMEM_BYTES>>>(q, ctx, w, hard);
}

// round 12
// speedup vs baseline: 1.4251x; 1.2127x over previous
#include <cuda_runtime.h>
#include <cuda_fp16.h>
#include <math.h>
#include <stdint.h>

#define DDIM 256
#define PDIM 64
#define MTILE 64
#define NTHREADS 256

#define KQP 144   // split buffers [64][64k] fp16 + 16B pad
#define SP  272   // sims [64 m][64 p] f32 + pad
#define WP  144   // W splits [64 m][64 p] fp16 + pad

// ---- smem offsets ----
#define QH_O 0
#define QL_O 9216
#define CH_O 18432
#define CL_O 27648
#define S_O  36864        // sims [64][272] f32 (disjoint from everything below)
#define WH_O 54272
#define WL_O 63488
#define C2_O 0            // GEMM2 C buffers alias Q/C region (dead after GEMM1)
#define C2STRIDE 18432
#define QSS_O 72704
#define CISM_O 72960
#define NEGM_O 73216
#define SMEM_BYTES 73472

__device__ __align__(16) unsigned short gCH[PDIM * DDIM];
__device__ __align__(16) unsigned short gCL[PDIM * DDIM];
__device__ float gCISM[PDIM];
__device__ float gNEGM[PDIM];

__device__ __forceinline__ uint32_t smem_u32(const void* p) {
    uint32_t a;
    asm("{ .reg .u64 t; cvta.to.shared.u64 t, %1; cvt.u32.u64 %0, t; }" : "=r"(a) : "l"(p));
    return a;
}
#define CPA16(dst, src) \
    asm volatile("cp.async.cg.shared.global [%0], [%1], 16;" :: "r"(dst), "l"(src) : "memory")
#define CPA_COMMIT() asm volatile("cp.async.commit_group;" ::: "memory")
#define CPA_WAIT0()  asm volatile("cp.async.wait_group 0;" ::: "memory")
#define CPA_WAIT1()  asm volatile("cp.async.wait_group 1;" ::: "memory")

__device__ __forceinline__ void ldsm4(uint32_t addr, uint32_t& r0, uint32_t& r1,
                                      uint32_t& r2, uint32_t& r3) {
    asm volatile("ldmatrix.sync.aligned.m8n8.x4.shared.b16 {%0,%1,%2,%3}, [%4];"
                 : "=r"(r0), "=r"(r1), "=r"(r2), "=r"(r3) : "r"(addr));
}
__device__ __forceinline__ void ldsm4t(uint32_t addr, uint32_t& r0, uint32_t& r1,
                                       uint32_t& r2, uint32_t& r3) {
    asm volatile("ldmatrix.sync.aligned.m8n8.x4.trans.shared.b16 {%0,%1,%2,%3}, [%4];"
                 : "=r"(r0), "=r"(r1), "=r"(r2), "=r"(r3) : "r"(addr));
}
__device__ __forceinline__ void mma16816(float* d, uint32_t a0, uint32_t a1, uint32_t a2,
                                         uint32_t a3, uint32_t b0, uint32_t b1) {
    asm volatile("mma.sync.aligned.m16n8k16.row.col.f32.f16.f16.f32 "
                 "{%0,%1,%2,%3}, {%4,%5,%6,%7}, {%8,%9}, {%0,%1,%2,%3};"
                 : "+f"(d[0]), "+f"(d[1]), "+f"(d[2]), "+f"(d[3])
                 : "r"(a0), "r"(a1), "r"(a2), "r"(a3), "r"(b0), "r"(b1));
}
// 4 MMAs: 32 rows (a0..a7) x 16 cols (e0..e3)
#define MMA4(acc, a0,a1,a2,a3,a4,a5,a6,a7, e0,e1,e2,e3) do { \
    mma16816((acc)[0], a0,a1,a2,a3, e0,e2); \
    mma16816((acc)[1], a0,a1,a2,a3, e1,e3); \
    mma16816((acc)[2], a4,a5,a6,a7, e0,e2); \
    mma16816((acc)[3], a4,a5,a6,a7, e1,e3); \
} while (0)

// packed f16x2 convert (cvt.rn, same as __float2half): x1 -> hi, x0 -> lo
__device__ __forceinline__ uint32_t cvt2h(float x1, float x0) {
    uint32_t r;
    asm("cvt.rn.f16x2.f32 %0, %1, %2;" : "=r"(r) : "f"(x1), "f"(x0));
    return r;
}
__device__ __forceinline__ float2 h2f2(uint32_t p) {
    __half2 h = *reinterpret_cast<__half2*>(&p);
    return __half22float2(h);
}

// 8 fp32 -> fp16 hi/lo splits (16B each); accumulate sumsq
__device__ __forceinline__ void conv8h(const float4* src, char* dh, char* dl,
                                       uint32_t off, float& acc) {
    float4 a = src[0], b = src[1];
    float xs[8] = {a.x, a.y, a.z, a.w, b.x, b.y, b.z, b.w};
    uint32_t H[4], L[4];
    #pragma unroll
    for (int i = 0; i < 4; ++i) {
        float x0 = xs[2 * i], x1 = xs[2 * i + 1];
        acc = fmaf(x0, x0, acc);
        acc = fmaf(x1, x1, acc);
        uint32_t h = cvt2h(x1, x0);
        float2 hf = h2f2(h);
        H[i] = h;
        L[i] = cvt2h(x1 - hf.y, x0 - hf.x);
    }
    *(uint4*)(dh + off) = make_uint4(H[0], H[1], H[2], H[3]);
    *(uint4*)(dl + off) = make_uint4(L[0], L[1], L[2], L[3]);
}

// ================= prep kernel: fp16-split C once, norms + mask =================
__global__ void centroid_prep(const float* __restrict__ gc, const int* __restrict__ gmask) {
    const int t = threadIdx.x;           // 256
    const int row = t >> 2, seg = t & 3;
    float acc = 0.f;
    #pragma unroll
    for (int j = 0; j < 8; ++j) {
        const float4* src = (const float4*)(gc + (size_t)row * DDIM + seg * 64 + j * 8);
        float4 a = src[0], b = src[1];
        float xs[8] = {a.x, a.y, a.z, a.w, b.x, b.y, b.z, b.w};
        uint32_t H[4], L[4];
        #pragma unroll
        for (int i = 0; i < 4; ++i) {
            float x0 = xs[2 * i], x1 = xs[2 * i + 1];
            acc = fmaf(x0, x0, acc);
            acc = fmaf(x1, x1, acc);
            uint32_t h = cvt2h(x1, x0);
            float2 hf = h2f2(h);
            H[i] = h;
            L[i] = cvt2h(x1 - hf.y, x0 - hf.x);
        }
        const int idx = row * DDIM + seg * 64 + j * 8;
        *(uint4*)(gCH + idx) = make_uint4(H[0], H[1], H[2], H[3]);
        *(uint4*)(gCL + idx) = make_uint4(L[0], L[1], L[2], L[3]);
    }
    acc += __shfl_xor_sync(0xffffffffu, acc, 1);
    acc += __shfl_xor_sync(0xffffffffu, acc, 2);
    if (seg == 0) {
        int mk = gmask[row];
        gCISM[row] = mk ? rsqrtf(fmaxf(acc, 1e-24f)) : 0.f;
        gNEGM[row] = mk ? 0.f : -1e9f;
    }
}

// cp.async one quarter (128B/row) of a precomputed split into pitched smem
__device__ __forceinline__ void copy_cq(uint32_t dstbase, const unsigned short* gsrc,
                                        int row, int seg, int kq) {
    uint32_t dst = dstbase + (uint32_t)(row * KQP + seg * 32);
    uint64_t src = __cvta_generic_to_global(gsrc + row * DDIM + kq * 64 + seg * 16);
    CPA16(dst, src);
    CPA16(dst + 16, src + 16);
}

__global__ void __launch_bounds__(NTHREADS, 3)
centroid_main(const float* __restrict__ gq,
              float* __restrict__ gctx,
              float* __restrict__ gw,
              float* __restrict__ ghard)
{
    extern __shared__ char sm[];
    const uint32_t smb = smem_u32(sm);
    const int t = threadIdx.x;
    const int wid = t >> 5, lane = t & 31;
    const int mbase = blockIdx.x * MTILE;

    float* qssf = (float*)(sm + QSS_O);
    float* cism = (float*)(sm + CISM_O);
    float* negm = (float*)(sm + NEGM_O);

    // GEMM1 warp mapping: 2M x 4N grid of 32x16 tiles, every warp does all 3 passes
    const int mrow = (wid & 1) * 32;
    const int ncol = (wid >> 1) * 16;
    const int row4 = t >> 2, seg4 = t & 3;

    if (t < 64) {
        cism[t] = gCISM[t];
        negm[t] = gNEGM[t];
    }

    float qacc = 0.f;
    float acc[4][4];
    #pragma unroll
    for (int i = 0; i < 4; ++i)
        #pragma unroll
        for (int j = 0; j < 4; ++j) acc[i][j] = 0.f;

    const uint32_t lrow = (uint32_t)(lane & 15);
    const uint32_t lk = (uint32_t)((lane >> 4) * 16);

    // ================= GEMM1 over four K-quarters, 3 fp16 split passes =================
    #pragma unroll 1
    for (int kq = 0; kq < 4; ++kq) {
        copy_cq(smb + CH_O, gCH, row4, seg4, kq);
        copy_cq(smb + CL_O, gCL, row4, seg4, kq);
        CPA_COMMIT();
        {
            const float4* src = (const float4*)(gq + (size_t)(mbase + row4) * DDIM + kq * 64 + seg4 * 16);
            uint32_t base = (uint32_t)(row4 * KQP + seg4 * 32);
            conv8h(src,     sm + QH_O, sm + QL_O, base,      qacc);
            conv8h(src + 2, sm + QH_O, sm + QL_O, base + 16, qacc);
        }
        if (kq == 3) {
            qacc += __shfl_xor_sync(0xffffffffu, qacc, 1);
            qacc += __shfl_xor_sync(0xffffffffu, qacc, 2);
            if (seg4 == 0) qssf[row4] = qacc;
        }
        CPA_WAIT0();
        __syncthreads();

        const uint32_t aQH = smb + QH_O + (mrow + lrow) * KQP + lk;
        const uint32_t aQL = smb + QL_O + (mrow + lrow) * KQP + lk;
        const uint32_t bCH = smb + CH_O + (ncol + lrow) * KQP + lk;
        const uint32_t bCL = smb + CL_O + (ncol + lrow) * KQP + lk;
        #pragma unroll
        for (int ks = 0; ks < 4; ++ks) {
            uint32_t a0, a1, a2, a3, a4, a5, a6, a7;
            uint32_t e0, e1, e2, e3, u0, u1, u2, u3;
            ldsm4(aQH + ks * 32, a0, a1, a2, a3);
            ldsm4(aQH + 16 * KQP + ks * 32, a4, a5, a6, a7);
            ldsm4(bCH + ks * 32, e0, e1, e2, e3);              // CH frags, held
            MMA4(acc, a0,a1,a2,a3,a4,a5,a6,a7, e0,e1,e2,e3);   // QH x CH
            ldsm4(bCL + ks * 32, u0, u1, u2, u3);
            MMA4(acc, a0,a1,a2,a3,a4,a5,a6,a7, u0,u1,u2,u3);   // QH x CL
            ldsm4(aQL + ks * 32, a0, a1, a2, a3);
            ldsm4(aQL + 16 * KQP + ks * 32, a4, a5, a6, a7);
            MMA4(acc, a0,a1,a2,a3,a4,a5,a6,a7, e0,e1,e2,e3);   // QL x CH
        }
        __syncthreads();
    }

    // ---- store sims (full tile per warp, no partials) ----
    {
        const int r0 = mrow + (lane >> 2);
        const int cb = ncol + (lane & 3) * 2;
        #pragma unroll
        for (int mf = 0; mf < 2; ++mf)
            #pragma unroll
            for (int nf = 0; nf < 2; ++nf) {
                float* a = acc[mf * 2 + nf];
                *(float2*)(sm + S_O + (r0 + mf * 16) * SP + (cb + nf * 8) * 4) = make_float2(a[0], a[1]);
                *(float2*)(sm + S_O + (r0 + mf * 16 + 8) * SP + (cb + nf * 8) * 4) = make_float2(a[2], a[3]);
            }
    }
    __syncthreads();

    // ---- prefetch GEMM2 d-quarter 0 into buffer 0 (Q/C region is dead) ----
    copy_cq(smb + C2_O, gCH, row4, seg4, 0);
    copy_cq(smb + C2_O + 9216, gCL, row4, seg4, 0);
    CPA_COMMIT();

    // ================= softmax + argmax: 4 threads per row =================
    {
        const int m = t >> 2, part = t & 3;
        const float qr = rsqrtf(fmaxf(qssf[m], 1e-24f));
        const float4* s0 = (const float4*)(sm + S_O + m * SP) + part * 4;
        float s[16];
        float mx = -INFINITY;
        int mi = PDIM;
        #pragma unroll
        for (int gg = 0; gg < 4; ++gg) {
            float4 v = s0[gg];
            float vv[4] = {v.x, v.y, v.z, v.w};
            #pragma unroll
            for (int i = 0; i < 4; ++i) {
                int p = part * 16 + gg * 4 + i;
                float val = fmaf(vv[i] * qr, cism[p], negm[p]);
                s[gg * 4 + i] = val;
                if (val > mx) { mx = val; mi = p; }     // strict >: first index wins
            }
        }
        #pragma unroll
        for (int off = 1; off < 4; off <<= 1) {
            float omx = __shfl_xor_sync(0xffffffffu, mx, off);
            int   omi = __shfl_xor_sync(0xffffffffu, mi, off);
            if (omx > mx || (omx == mx && omi < mi)) { mx = omx; mi = omi; }
        }
        float ssum = 0.f;
        #pragma unroll
        for (int i = 0; i < 16; ++i) {
            float e = expf(s[i] - mx);
            s[i] = e;
            ssum += e;
        }
        #pragma unroll
        for (int off = 1; off < 4; off <<= 1)
            ssum += __shfl_xor_sync(0xffffffffu, ssum, off);
        const float inv = 1.0f / ssum;

        float4* gwp = (float4*)(gw + (size_t)(mbase + m) * PDIM + part * 16);
        char* wh = sm + WH_O + m * WP + part * 32;
        char* wl = sm + WL_O + m * WP + part * 32;
        #pragma unroll
        for (int gg = 0; gg < 2; ++gg) {
            float w0 = s[8 * gg + 0] * inv, w1 = s[8 * gg + 1] * inv;
            float w2 = s[8 * gg + 2] * inv, w3 = s[8 * gg + 3] * inv;
            float w4 = s[8 * gg + 4] * inv, w5 = s[8 * gg + 5] * inv;
            float w6 = s[8 * gg + 6] * inv, w7 = s[8 * gg + 7] * inv;
            gwp[2 * gg]     = make_float4(w0, w1, w2, w3);
            gwp[2 * gg + 1] = make_float4(w4, w5, w6, w7);
            uint32_t h0 = cvt2h(w1, w0), h1 = cvt2h(w3, w2);
            uint32_t h2 = cvt2h(w5, w4), h3 = cvt2h(w7, w6);
            float2 f0 = h2f2(h0), f1 = h2f2(h1), f2 = h2f2(h2), f3 = h2f2(h3);
            uint32_t l0 = cvt2h(w1 - f0.y, w0 - f0.x);
            uint32_t l1 = cvt2h(w3 - f1.y, w2 - f1.x);
            uint32_t l2 = cvt2h(w5 - f2.y, w4 - f2.x);
            uint32_t l3 = cvt2h(w7 - f3.y, w6 - f3.x);
            *(uint4*)(wh + gg * 16) = make_uint4(h0, h1, h2, h3);
            *(uint4*)(wl + gg * 16) = make_uint4(l0, l1, l2, l3);
        }
        if (part == 0) ghard[mbase + m] = (float)mi;
    }
    __syncthreads();

    // ================= GEMM2: 4 d-quarter rounds, double-buffered, 3 fp16 passes =================
    {
        const int mrow2 = (wid & 1) * 32;
        const int dt = (wid >> 1) * 16;
        const uint32_t btrow = (uint32_t)((lane >> 4) * 8 + (lane & 7));
        const uint32_t btcol = (uint32_t)(((lane >> 3) & 1) * 16);
        const uint32_t aWHr = smb + WH_O + (mrow2 + lrow) * WP + lk;
        const uint32_t aWLr = smb + WL_O + (mrow2 + lrow) * WP + lk;

        #pragma unroll 1
        for (int dq = 0; dq < 4; ++dq) {
            const uint32_t cbuf = C2_O + (uint32_t)(dq & 1) * C2STRIDE;
            if (dq < 3) {
                const uint32_t nbuf = C2_O + (uint32_t)((dq + 1) & 1) * C2STRIDE;
                copy_cq(smb + nbuf, gCH, row4, seg4, dq + 1);
                copy_cq(smb + nbuf + 9216, gCL, row4, seg4, dq + 1);
                CPA_COMMIT();
                CPA_WAIT1();
            } else {
                CPA_WAIT0();
            }
            __syncthreads();

            float dd[4][4];
            #pragma unroll
            for (int i = 0; i < 4; ++i)
                #pragma unroll
                for (int j = 0; j < 4; ++j) dd[i][j] = 0.f;

            const uint32_t bC2H = smb + cbuf + btrow * KQP + dt * 2 + btcol;
            const uint32_t bC2L = bC2H + 9216;
            #pragma unroll
            for (int ks = 0; ks < 4; ++ks) {
                uint32_t a0, a1, a2, a3, a4, a5, a6, a7;
                uint32_t r0, r1, r2, r3, s0, s1, s2, s3;
                ldsm4(aWHr + ks * 32, a0, a1, a2, a3);
                ldsm4(aWHr + 16 * WP + ks * 32, a4, a5, a6, a7);
                ldsm4t(bC2H + ks * 16 * KQP, r0, r1, r2, r3);   // CH frags, held
                mma16816(dd[0], a0, a1, a2, a3, r0, r2);
                mma16816(dd[1], a0, a1, a2, a3, r1, r3);
                mma16816(dd[2], a4, a5, a6, a7, r0, r2);
                mma16816(dd[3], a4, a5, a6, a7, r1, r3);
                ldsm4t(bC2L + ks * 16 * KQP, s0, s1, s2, s3);
                mma16816(dd[0], a0, a1, a2, a3, s0, s2);
                mma16816(dd[1], a0, a1, a2, a3, s1, s3);
                mma16816(dd[2], a4, a5, a6, a7, s0, s2);
                mma16816(dd[3], a4, a5, a6, a7, s1, s3);
                ldsm4(aWLr + ks * 32, a0, a1, a2, a3);
                ldsm4(aWLr + 16 * WP + ks * 32, a4, a5, a6, a7);
                mma16816(dd[0], a0, a1, a2, a3, r0, r2);
                mma16816(dd[1], a0, a1, a2, a3, r1, r3);
                mma16816(dd[2], a4, a5, a6, a7, r0, r2);
                mma16816(dd[3], a4, a5, a6, a7, r1, r3);
            }
            const int r0l = lane >> 2;
            const int cb = dq * 64 + dt + (lane & 3) * 2;
            #pragma unroll
            for (int mf = 0; mf < 2; ++mf) {
                float* gr0 = gctx + (size_t)(mbase + mrow2 + mf * 16 + r0l) * DDIM;
                float* gr1 = gr0 + 8 * DDIM;
                #pragma unroll
                for (int nf = 0; nf < 2; ++nf) {
                    float* a = dd[mf * 2 + nf];
                    *(float2*)(gr0 + cb + nf * 8) = make_float2(a[0], a[1]);
                    *(float2*)(gr1 + cb + nf * 8) = make_float2(a[2], a[3]);
                }
            }
            __syncthreads();
        }
    }
}

extern "C" void kernel_launch(void* const* d_in, const int* in_sizes, int n_in,
                              void* d_out, int out_size)
{
    const float* q = (const float*)d_in[0];
    const float* c = (const float*)d_in[1];
    const int*   mask = (const int*)d_in[2];

    const int Pn = in_sizes[2];              // 64
    const int Dn = in_sizes[1] / Pn;         // 256
    const int B  = in_sizes[0] / Dn;         // 131072

    float* out  = (float*)d_out;
    float* ctx  = out;                           // [B, D]
    float* w    = out + (size_t)B * Dn;          // [B, P]
    float* hard = w + (size_t)B * Pn;            // [B]

    centroid_prep<<<1, 256>>>(c, mask);
    cudaFuncSetAttribute(centroid_main,
                         cudaFuncAttributeMaxDynamicSharedMemorySize, SMEM_BYTES);
    centroid_main<<<B / MTILE, NTHREADS, SMEM_BYTES>>>(q, ctx, w, hard);
}

// round 13
// speedup vs baseline: 1.6171x; 1.1347x over previous
#include <cuda_runtime.h>
#include <cuda_fp16.h>
#include <math.h>
#include <stdint.h>

#define DDIM 256
#define PDIM 64
#define MTILE 64
#define NTHREADS 256

#define KQP 144   // split buffers [64][64k] fp16 + 16B pad
#define SP  272   // sims [64 m][64 p] f32 + pad
#define WP  144   // W fp16 [64 m][64 p] + pad

// ---- smem offsets ----
#define QH_O 0
#define QL_O 9216
#define CH_O 18432
#define CL_O 27648
#define S_O  36864        // sims [64][272] f32 (disjoint from C2 buffers below)
#define WH_O 54272        // W fp16 (single, no split)
#define C2_O 0            // GEMM2 C buffers alias Q/C region (dead after GEMM1)
#define C2STRIDE 18432
#define QSS_O 63488
#define CISM_O 63744
#define NEGM_O 64000
#define SMEM_BYTES 64256

__device__ __align__(16) unsigned short gCH[PDIM * DDIM];
__device__ __align__(16) unsigned short gCL[PDIM * DDIM];
__device__ float gCISM[PDIM];
__device__ float gNEGM[PDIM];

__device__ __forceinline__ uint32_t smem_u32(const void* p) {
    uint32_t a;
    asm("{ .reg .u64 t; cvta.to.shared.u64 t, %1; cvt.u32.u64 %0, t; }" : "=r"(a) : "l"(p));
    return a;
}
#define CPA16(dst, src) \
    asm volatile("cp.async.cg.shared.global [%0], [%1], 16;" :: "r"(dst), "l"(src) : "memory")
#define CPA_COMMIT() asm volatile("cp.async.commit_group;" ::: "memory")
#define CPA_WAIT0()  asm volatile("cp.async.wait_group 0;" ::: "memory")
#define CPA_WAIT1()  asm volatile("cp.async.wait_group 1;" ::: "memory")

__device__ __forceinline__ void ldsm4(uint32_t addr, uint32_t& r0, uint32_t& r1,
                                      uint32_t& r2, uint32_t& r3) {
    asm volatile("ldmatrix.sync.aligned.m8n8.x4.shared.b16 {%0,%1,%2,%3}, [%4];"
                 : "=r"(r0), "=r"(r1), "=r"(r2), "=r"(r3) : "r"(addr));
}
__device__ __forceinline__ void ldsm4t(uint32_t addr, uint32_t& r0, uint32_t& r1,
                                       uint32_t& r2, uint32_t& r3) {
    asm volatile("ldmatrix.sync.aligned.m8n8.x4.trans.shared.b16 {%0,%1,%2,%3}, [%4];"
                 : "=r"(r0), "=r"(r1), "=r"(r2), "=r"(r3) : "r"(addr));
}
__device__ __forceinline__ void mma16816(float* d, uint32_t a0, uint32_t a1, uint32_t a2,
                                         uint32_t a3, uint32_t b0, uint32_t b1) {
    asm volatile("mma.sync.aligned.m16n8k16.row.col.f32.f16.f16.f32 "
                 "{%0,%1,%2,%3}, {%4,%5,%6,%7}, {%8,%9}, {%0,%1,%2,%3};"
                 : "+f"(d[0]), "+f"(d[1]), "+f"(d[2]), "+f"(d[3])
                 : "r"(a0), "r"(a1), "r"(a2), "r"(a3), "r"(b0), "r"(b1));
}
// 4 MMAs: 32 rows (a0..a7) x 16 cols (e0..e3)
#define MMA4(acc, a0,a1,a2,a3,a4,a5,a6,a7, e0,e1,e2,e3) do { \
    mma16816((acc)[0], a0,a1,a2,a3, e0,e2); \
    mma16816((acc)[1], a0,a1,a2,a3, e1,e3); \
    mma16816((acc)[2], a4,a5,a6,a7, e0,e2); \
    mma16816((acc)[3], a4,a5,a6,a7, e1,e3); \
} while (0)

// packed f16x2 convert (cvt.rn, same as __float2half): x1 -> hi, x0 -> lo
__device__ __forceinline__ uint32_t cvt2h(float x1, float x0) {
    uint32_t r;
    asm("cvt.rn.f16x2.f32 %0, %1, %2;" : "=r"(r) : "f"(x1), "f"(x0));
    return r;
}
__device__ __forceinline__ float2 h2f2(uint32_t p) {
    __half2 h = *reinterpret_cast<__half2*>(&p);
    return __half22float2(h);
}

// 8 fp32 -> fp16 hi/lo splits (16B each); accumulate sumsq
__device__ __forceinline__ void conv8h(const float4* src, char* dh, char* dl,
                                       uint32_t off, float& acc) {
    float4 a = src[0], b = src[1];
    float xs[8] = {a.x, a.y, a.z, a.w, b.x, b.y, b.z, b.w};
    uint32_t H[4], L[4];
    #pragma unroll
    for (int i = 0; i < 4; ++i) {
        float x0 = xs[2 * i], x1 = xs[2 * i + 1];
        acc = fmaf(x0, x0, acc);
        acc = fmaf(x1, x1, acc);
        uint32_t h = cvt2h(x1, x0);
        float2 hf = h2f2(h);
        H[i] = h;
        L[i] = cvt2h(x1 - hf.y, x0 - hf.x);
    }
    *(uint4*)(dh + off) = make_uint4(H[0], H[1], H[2], H[3]);
    *(uint4*)(dl + off) = make_uint4(L[0], L[1], L[2], L[3]);
}

// ================= prep kernel: fp16-split C once, norms + mask =================
// <<<8, 256>>>: one warp per centroid row, 8 elems per lane
__global__ void centroid_prep(const float* __restrict__ gc, const int* __restrict__ gmask) {
    const int wid = threadIdx.x >> 5, lane = threadIdx.x & 31;
    const int row = blockIdx.x * 8 + wid;
    const float4* src = (const float4*)(gc + (size_t)row * DDIM) + lane * 2;
    float4 a = src[0], b = src[1];
    float xs[8] = {a.x, a.y, a.z, a.w, b.x, b.y, b.z, b.w};
    float acc = 0.f;
    uint32_t H[4], L[4];
    #pragma unroll
    for (int i = 0; i < 4; ++i) {
        float x0 = xs[2 * i], x1 = xs[2 * i + 1];
        acc = fmaf(x0, x0, acc);
        acc = fmaf(x1, x1, acc);
        uint32_t h = cvt2h(x1, x0);
        float2 hf = h2f2(h);
        H[i] = h;
        L[i] = cvt2h(x1 - hf.y, x0 - hf.x);
    }
    const int idx = row * DDIM + lane * 8;
    *(uint4*)(gCH + idx) = make_uint4(H[0], H[1], H[2], H[3]);
    *(uint4*)(gCL + idx) = make_uint4(L[0], L[1], L[2], L[3]);
    #pragma unroll
    for (int off = 1; off < 32; off <<= 1)
        acc += __shfl_xor_sync(0xffffffffu, acc, off);
    if (lane == 0) {
        int mk = gmask[row];
        gCISM[row] = mk ? rsqrtf(fmaxf(acc, 1e-24f)) : 0.f;
        gNEGM[row] = mk ? 0.f : -1e9f;
    }
}

// cp.async one quarter (128B/row) of a precomputed split into pitched smem
__device__ __forceinline__ void copy_cq(uint32_t dstbase, const unsigned short* gsrc,
                                        int row, int seg, int kq) {
    uint32_t dst = dstbase + (uint32_t)(row * KQP + seg * 32);
    uint64_t src = __cvta_generic_to_global(gsrc + row * DDIM + kq * 64 + seg * 16);
    CPA16(dst, src);
    CPA16(dst + 16, src + 16);
}

__global__ void __launch_bounds__(NTHREADS, 3)
centroid_main(const float* __restrict__ gq,
              float* __restrict__ gctx,
              float* __restrict__ gw,
              float* __restrict__ ghard)
{
    extern __shared__ char sm[];
    const uint32_t smb = smem_u32(sm);
    const int t = threadIdx.x;
    const int wid = t >> 5, lane = t & 31;
    const int mbase = blockIdx.x * MTILE;

    float* qssf = (float*)(sm + QSS_O);
    float* cism = (float*)(sm + CISM_O);
    float* negm = (float*)(sm + NEGM_O);

    // GEMM1 warp mapping: 2M x 4N grid of 32x16 tiles, every warp does all 3 passes
    const int mrow = (wid & 1) * 32;
    const int ncol = (wid >> 1) * 16;
    const int row4 = t >> 2, seg4 = t & 3;

    if (t < 64) {
        cism[t] = gCISM[t];
        negm[t] = gNEGM[t];
    }

    float qacc = 0.f;
    float acc[4][4];
    #pragma unroll
    for (int i = 0; i < 4; ++i)
        #pragma unroll
        for (int j = 0; j < 4; ++j) acc[i][j] = 0.f;

    const uint32_t lrow = (uint32_t)(lane & 15);
    const uint32_t lk = (uint32_t)((lane >> 4) * 16);

    // ================= GEMM1 over four K-quarters, 3 fp16 split passes =================
    #pragma unroll 1
    for (int kq = 0; kq < 4; ++kq) {
        copy_cq(smb + CH_O, gCH, row4, seg4, kq);
        copy_cq(smb + CL_O, gCL, row4, seg4, kq);
        CPA_COMMIT();
        {
            const float4* src = (const float4*)(gq + (size_t)(mbase + row4) * DDIM + kq * 64 + seg4 * 16);
            uint32_t base = (uint32_t)(row4 * KQP + seg4 * 32);
            conv8h(src,     sm + QH_O, sm + QL_O, base,      qacc);
            conv8h(src + 2, sm + QH_O, sm + QL_O, base + 16, qacc);
        }
        if (kq == 3) {
            qacc += __shfl_xor_sync(0xffffffffu, qacc, 1);
            qacc += __shfl_xor_sync(0xffffffffu, qacc, 2);
            if (seg4 == 0) qssf[row4] = qacc;
        }
        CPA_WAIT0();
        __syncthreads();

        const uint32_t aQH = smb + QH_O + (mrow + lrow) * KQP + lk;
        const uint32_t aQL = smb + QL_O + (mrow + lrow) * KQP + lk;
        const uint32_t bCH = smb + CH_O + (ncol + lrow) * KQP + lk;
        const uint32_t bCL = smb + CL_O + (ncol + lrow) * KQP + lk;
        #pragma unroll
        for (int ks = 0; ks < 4; ++ks) {
            uint32_t a0, a1, a2, a3, a4, a5, a6, a7;
            uint32_t e0, e1, e2, e3, u0, u1, u2, u3;
            ldsm4(aQH + ks * 32, a0, a1, a2, a3);
            ldsm4(aQH + 16 * KQP + ks * 32, a4, a5, a6, a7);
            ldsm4(bCH + ks * 32, e0, e1, e2, e3);              // CH frags, held
            MMA4(acc, a0,a1,a2,a3,a4,a5,a6,a7, e0,e1,e2,e3);   // QH x CH
            ldsm4(bCL + ks * 32, u0, u1, u2, u3);
            MMA4(acc, a0,a1,a2,a3,a4,a5,a6,a7, u0,u1,u2,u3);   // QH x CL
            ldsm4(aQL + ks * 32, a0, a1, a2, a3);
            ldsm4(aQL + 16 * KQP + ks * 32, a4, a5, a6, a7);
            MMA4(acc, a0,a1,a2,a3,a4,a5,a6,a7, e0,e1,e2,e3);   // QL x CH
        }
        __syncthreads();
    }

    // ---- store sims (full tile per warp) ----
    {
        const int r0 = mrow + (lane >> 2);
        const int cb = ncol + (lane & 3) * 2;
        #pragma unroll
        for (int mf = 0; mf < 2; ++mf)
            #pragma unroll
            for (int nf = 0; nf < 2; ++nf) {
                float* a = acc[mf * 2 + nf];
                *(float2*)(sm + S_O + (r0 + mf * 16) * SP + (cb + nf * 8) * 4) = make_float2(a[0], a[1]);
                *(float2*)(sm + S_O + (r0 + mf * 16 + 8) * SP + (cb + nf * 8) * 4) = make_float2(a[2], a[3]);
            }
    }
    __syncthreads();

    // ---- prefetch GEMM2 d-quarter 0 into buffer 0 (Q/C region is dead) ----
    copy_cq(smb + C2_O, gCH, row4, seg4, 0);
    copy_cq(smb + C2_O + 9216, gCL, row4, seg4, 0);
    CPA_COMMIT();

    // ================= softmax + argmax: 4 threads per row =================
    {
        const int m = t >> 2, part = t & 3;
        const float qr = rsqrtf(fmaxf(qssf[m], 1e-24f));
        const float4* s0 = (const float4*)(sm + S_O + m * SP) + part * 4;
        float s[16];
        float mx = -INFINITY;
        int mi = PDIM;
        #pragma unroll
        for (int gg = 0; gg < 4; ++gg) {
            float4 v = s0[gg];
            float vv[4] = {v.x, v.y, v.z, v.w};
            #pragma unroll
            for (int i = 0; i < 4; ++i) {
                int p = part * 16 + gg * 4 + i;
                float val = fmaf(vv[i] * qr, cism[p], negm[p]);
                s[gg * 4 + i] = val;
                if (val > mx) { mx = val; mi = p; }     // strict >: first index wins
            }
        }
        #pragma unroll
        for (int off = 1; off < 4; off <<= 1) {
            float omx = __shfl_xor_sync(0xffffffffu, mx, off);
            int   omi = __shfl_xor_sync(0xffffffffu, mi, off);
            if (omx > mx || (omx == mx && omi < mi)) { mx = omx; mi = omi; }
        }
        float ssum = 0.f;
        #pragma unroll
        for (int i = 0; i < 16; ++i) {
            float e = expf(s[i] - mx);
            s[i] = e;
            ssum += e;
        }
        #pragma unroll
        for (int off = 1; off < 4; off <<= 1)
            ssum += __shfl_xor_sync(0xffffffffu, ssum, off);
        const float inv = 1.0f / ssum;

        float4* gwp = (float4*)(gw + (size_t)(mbase + m) * PDIM + part * 16);
        char* wh = sm + WH_O + m * WP + part * 32;
        #pragma unroll
        for (int gg = 0; gg < 2; ++gg) {
            float w0 = s[8 * gg + 0] * inv, w1 = s[8 * gg + 1] * inv;
            float w2 = s[8 * gg + 2] * inv, w3 = s[8 * gg + 3] * inv;
            float w4 = s[8 * gg + 4] * inv, w5 = s[8 * gg + 5] * inv;
            float w6 = s[8 * gg + 6] * inv, w7 = s[8 * gg + 7] * inv;
            gwp[2 * gg]     = make_float4(w0, w1, w2, w3);
            gwp[2 * gg + 1] = make_float4(w4, w5, w6, w7);
            uint32_t h0 = cvt2h(w1, w0), h1 = cvt2h(w3, w2);
            uint32_t h2 = cvt2h(w5, w4), h3 = cvt2h(w7, w6);
            *(uint4*)(wh + gg * 16) = make_uint4(h0, h1, h2, h3);
        }
        if (part == 0) ghard[mbase + m] = (float)mi;
    }
    __syncthreads();

    // ================= GEMM2: 4 d-quarter rounds, double-buffered, 2 fp16 passes =================
    {
        const int mrow2 = (wid & 1) * 32;
        const int dt = (wid >> 1) * 16;
        const uint32_t btrow = (uint32_t)((lane >> 4) * 8 + (lane & 7));
        const uint32_t btcol = (uint32_t)(((lane >> 3) & 1) * 16);
        const uint32_t aWHr = smb + WH_O + (mrow2 + lrow) * WP + lk;

        #pragma unroll 1
        for (int dq = 0; dq < 4; ++dq) {
            const uint32_t cbuf = C2_O + (uint32_t)(dq & 1) * C2STRIDE;
            if (dq < 3) {
                const uint32_t nbuf = C2_O + (uint32_t)((dq + 1) & 1) * C2STRIDE;
                copy_cq(smb + nbuf, gCH, row4, seg4, dq + 1);
                copy_cq(smb + nbuf + 9216, gCL, row4, seg4, dq + 1);
                CPA_COMMIT();
                CPA_WAIT1();
            } else {
                CPA_WAIT0();
            }
            __syncthreads();

            float dd[4][4];
            #pragma unroll
            for (int i = 0; i < 4; ++i)
                #pragma unroll
                for (int j = 0; j < 4; ++j) dd[i][j] = 0.f;

            const uint32_t bC2H = smb + cbuf + btrow * KQP + dt * 2 + btcol;
            const uint32_t bC2L = bC2H + 9216;
            #pragma unroll
            for (int ks = 0; ks < 4; ++ks) {
                uint32_t a0, a1, a2, a3, a4, a5, a6, a7;
                uint32_t r0, r1, r2, r3, s0, s1, s2, s3;
                ldsm4(aWHr + ks * 32, a0, a1, a2, a3);
                ldsm4(aWHr + 16 * WP + ks * 32, a4, a5, a6, a7);
                ldsm4t(bC2H + ks * 16 * KQP, r0, r1, r2, r3);
                mma16816(dd[0], a0, a1, a2, a3, r0, r2);
                mma16816(dd[1], a0, a1, a2, a3, r1, r3);
                mma16816(dd[2], a4, a5, a6, a7, r0, r2);
                mma16816(dd[3], a4, a5, a6, a7, r1, r3);
                ldsm4t(bC2L + ks * 16 * KQP, s0, s1, s2, s3);
                mma16816(dd[0], a0, a1, a2, a3, s0, s2);
                mma16816(dd[1], a0, a1, a2, a3, s1, s3);
                mma16816(dd[2], a4, a5, a6, a7, s0, s2);
                mma16816(dd[3], a4, a5, a6, a7, s1, s3);
            }
            const int r0l = lane >> 2;
            const int cb = dq * 64 + dt + (lane & 3) * 2;
            #pragma unroll
            for (int mf = 0; mf < 2; ++mf) {
                float* gr0 = gctx + (size_t)(mbase + mrow2 + mf * 16 + r0l) * DDIM;
                float* gr1 = gr0 + 8 * DDIM;
                #pragma unroll
                for (int nf = 0; nf < 2; ++nf) {
                    float* a = dd[mf * 2 + nf];
                    *(float2*)(gr0 + cb + nf * 8) = make_float2(a[0], a[1]);
                    *(float2*)(gr1 + cb + nf * 8) = make_float2(a[2], a[3]);
                }
            }
            __syncthreads();
        }
    }
}

extern "C" void kernel_launch(void* const* d_in, const int* in_sizes, int n_in,
                              void* d_out, int out_size)
{
    const float* q = (const float*)d_in[0];
    const float* c = (const float*)d_in[1];
    const int*   mask = (const int*)d_in[2];

    const int Pn = in_sizes[2];              // 64
    const int Dn = in_sizes[1] / Pn;         // 256
    const int B  = in_sizes[0] / Dn;         // 131072

    float* out  = (float*)d_out;
    float* ctx  = out;                           // [B, D]
    float* w    = out + (size_t)B * Dn;          // [B, P]
    float* hard = w + (size_t)B * Pn;            // [B]

    centroid_prep<<<8, 256>>>(c, mask);
    cudaFuncSetAttribute(centroid_main,
                         cudaFuncAttributeMaxDynamicSharedMemorySize, SMEM_BYTES);
    centroid_main<<<B / MTILE, NTHREADS, SMEM_BYTES>>>(q, ctx, w, hard);
}

// round 14
// speedup vs baseline: 1.7532x; 1.0842x over previous
#include <cuda_runtime.h>
#include <cuda_fp16.h>
#include <math.h>
#include <stdint.h>

#define DDIM 256
#define PDIM 64
#define MTILE 64
#define NTHREADS 256

#define KQP 144   // split buffers [64][64k] fp16 + 16B pad
#define SP  272   // sims [64 m][64 p] f32 + pad
#define WP  144   // W fp16 [64 m][64 p] + pad

// ---- smem offsets ----
#define QH_O 0
#define QL_O 9216
#define CH_O 18432
#define CL_O 27648
#define S_O  36864        // sims [64][272] f32 (disjoint from C2 buffers below)
#define WH_O 54272        // W fp16 (single, no split)
#define C2_O 0            // GEMM2 C buffers alias Q/C region (dead after GEMM1)
#define C2STRIDE 9216     // single split now -> buffers at 0 and 9216
#define QSS_O 63488
#define CISM_O 63744
#define NEGM_O 64000
#define SMEM_BYTES 64256

__device__ __align__(16) unsigned short gCH[PDIM * DDIM];
__device__ __align__(16) unsigned short gCL[PDIM * DDIM];
__device__ float gCISM[PDIM];
__device__ float gNEGM[PDIM];

__device__ __forceinline__ uint32_t smem_u32(const void* p) {
    uint32_t a;
    asm("{ .reg .u64 t; cvta.to.shared.u64 t, %1; cvt.u32.u64 %0, t; }" : "=r"(a) : "l"(p));
    return a;
}
#define CPA16(dst, src) \
    asm volatile("cp.async.cg.shared.global [%0], [%1], 16;" :: "r"(dst), "l"(src) : "memory")
#define CPA_COMMIT() asm volatile("cp.async.commit_group;" ::: "memory")
#define CPA_WAIT0()  asm volatile("cp.async.wait_group 0;" ::: "memory")
#define CPA_WAIT1()  asm volatile("cp.async.wait_group 1;" ::: "memory")

__device__ __forceinline__ void ldsm4(uint32_t addr, uint32_t& r0, uint32_t& r1,
                                      uint32_t& r2, uint32_t& r3) {
    asm volatile("ldmatrix.sync.aligned.m8n8.x4.shared.b16 {%0,%1,%2,%3}, [%4];"
                 : "=r"(r0), "=r"(r1), "=r"(r2), "=r"(r3) : "r"(addr));
}
__device__ __forceinline__ void ldsm4t(uint32_t addr, uint32_t& r0, uint32_t& r1,
                                       uint32_t& r2, uint32_t& r3) {
    asm volatile("ldmatrix.sync.aligned.m8n8.x4.trans.shared.b16 {%0,%1,%2,%3}, [%4];"
                 : "=r"(r0), "=r"(r1), "=r"(r2), "=r"(r3) : "r"(addr));
}
__device__ __forceinline__ void mma16816(float* d, uint32_t a0, uint32_t a1, uint32_t a2,
                                         uint32_t a3, uint32_t b0, uint32_t b1) {
    asm volatile("mma.sync.aligned.m16n8k16.row.col.f32.f16.f16.f32 "
                 "{%0,%1,%2,%3}, {%4,%5,%6,%7}, {%8,%9}, {%0,%1,%2,%3};"
                 : "+f"(d[0]), "+f"(d[1]), "+f"(d[2]), "+f"(d[3])
                 : "r"(a0), "r"(a1), "r"(a2), "r"(a3), "r"(b0), "r"(b1));
}
// 4 MMAs: 32 rows (a0..a7) x 16 cols (e0..e3)
#define MMA4(acc, a0,a1,a2,a3,a4,a5,a6,a7, e0,e1,e2,e3) do { \
    mma16816((acc)[0], a0,a1,a2,a3, e0,e2); \
    mma16816((acc)[1], a0,a1,a2,a3, e1,e3); \
    mma16816((acc)[2], a4,a5,a6,a7, e0,e2); \
    mma16816((acc)[3], a4,a5,a6,a7, e1,e3); \
} while (0)

// packed f16x2 convert (cvt.rn, same as __float2half): x1 -> hi, x0 -> lo
__device__ __forceinline__ uint32_t cvt2h(float x1, float x0) {
    uint32_t r;
    asm("cvt.rn.f16x2.f32 %0, %1, %2;" : "=r"(r) : "f"(x1), "f"(x0));
    return r;
}
__device__ __forceinline__ float2 h2f2(uint32_t p) {
    __half2 h = *reinterpret_cast<__half2*>(&p);
    return __half22float2(h);
}

// 8 fp32 -> fp16 hi/lo splits (16B each); accumulate sumsq
__device__ __forceinline__ void conv8h(const float4* src, char* dh, char* dl,
                                       uint32_t off, float& acc) {
    float4 a = src[0], b = src[1];
    float xs[8] = {a.x, a.y, a.z, a.w, b.x, b.y, b.z, b.w};
    uint32_t H[4], L[4];
    #pragma unroll
    for (int i = 0; i < 4; ++i) {
        float x0 = xs[2 * i], x1 = xs[2 * i + 1];
        acc = fmaf(x0, x0, acc);
        acc = fmaf(x1, x1, acc);
        uint32_t h = cvt2h(x1, x0);
        float2 hf = h2f2(h);
        H[i] = h;
        L[i] = cvt2h(x1 - hf.y, x0 - hf.x);
    }
    *(uint4*)(dh + off) = make_uint4(H[0], H[1], H[2], H[3]);
    *(uint4*)(dl + off) = make_uint4(L[0], L[1], L[2], L[3]);
}

// ================= prep kernel: fp16-split C once, norms + mask =================
// <<<8, 256>>>: one warp per centroid row, 8 elems per lane
__global__ void centroid_prep(const float* __restrict__ gc, const int* __restrict__ gmask) {
    const int wid = threadIdx.x >> 5, lane = threadIdx.x & 31;
    const int row = blockIdx.x * 8 + wid;
    const float4* src = (const float4*)(gc + (size_t)row * DDIM) + lane * 2;
    float4 a = src[0], b = src[1];
    float xs[8] = {a.x, a.y, a.z, a.w, b.x, b.y, b.z, b.w};
    float acc = 0.f;
    uint32_t H[4], L[4];
    #pragma unroll
    for (int i = 0; i < 4; ++i) {
        float x0 = xs[2 * i], x1 = xs[2 * i + 1];
        acc = fmaf(x0, x0, acc);
        acc = fmaf(x1, x1, acc);
        uint32_t h = cvt2h(x1, x0);
        float2 hf = h2f2(h);
        H[i] = h;
        L[i] = cvt2h(x1 - hf.y, x0 - hf.x);
    }
    const int idx = row * DDIM + lane * 8;
    *(uint4*)(gCH + idx) = make_uint4(H[0], H[1], H[2], H[3]);
    *(uint4*)(gCL + idx) = make_uint4(L[0], L[1], L[2], L[3]);
    #pragma unroll
    for (int off = 1; off < 32; off <<= 1)
        acc += __shfl_xor_sync(0xffffffffu, acc, off);
    if (lane == 0) {
        int mk = gmask[row];
        gCISM[row] = mk ? rsqrtf(fmaxf(acc, 1e-24f)) : 0.f;
        gNEGM[row] = mk ? 0.f : -1e9f;
    }
}

// cp.async one quarter (128B/row) of a precomputed split into pitched smem
__device__ __forceinline__ void copy_cq(uint32_t dstbase, const unsigned short* gsrc,
                                        int row, int seg, int kq) {
    uint32_t dst = dstbase + (uint32_t)(row * KQP + seg * 32);
    uint64_t src = __cvta_generic_to_global(gsrc + row * DDIM + kq * 64 + seg * 16);
    CPA16(dst, src);
    CPA16(dst + 16, src + 16);
}

__global__ void __launch_bounds__(NTHREADS, 3)
centroid_main(const float* __restrict__ gq,
              float* __restrict__ gctx,
              float* __restrict__ gw,
              float* __restrict__ ghard)
{
    extern __shared__ char sm[];
    const uint32_t smb = smem_u32(sm);
    const int t = threadIdx.x;
    const int wid = t >> 5, lane = t & 31;
    const int mbase = blockIdx.x * MTILE;

    float* qssf = (float*)(sm + QSS_O);
    float* cism = (float*)(sm + CISM_O);
    float* negm = (float*)(sm + NEGM_O);

    // GEMM1 warp mapping: 2M x 4N grid of 32x16 tiles, every warp does all 3 passes
    const int mrow = (wid & 1) * 32;
    const int ncol = (wid >> 1) * 16;
    const int row4 = t >> 2, seg4 = t & 3;

    if (t < 64) {
        cism[t] = gCISM[t];
        negm[t] = gNEGM[t];
    }

    float qacc = 0.f;
    float acc[4][4];
    #pragma unroll
    for (int i = 0; i < 4; ++i)
        #pragma unroll
        for (int j = 0; j < 4; ++j) acc[i][j] = 0.f;

    const uint32_t lrow = (uint32_t)(lane & 15);
    const uint32_t lk = (uint32_t)((lane >> 4) * 16);

    // ================= GEMM1 over four K-quarters, 3 fp16 split passes =================
    #pragma unroll 1
    for (int kq = 0; kq < 4; ++kq) {
        copy_cq(smb + CH_O, gCH, row4, seg4, kq);
        copy_cq(smb + CL_O, gCL, row4, seg4, kq);
        CPA_COMMIT();
        {
            const float4* src = (const float4*)(gq + (size_t)(mbase + row4) * DDIM + kq * 64 + seg4 * 16);
            uint32_t base = (uint32_t)(row4 * KQP + seg4 * 32);
            conv8h(src,     sm + QH_O, sm + QL_O, base,      qacc);
            conv8h(src + 2, sm + QH_O, sm + QL_O, base + 16, qacc);
        }
        if (kq == 3) {
            qacc += __shfl_xor_sync(0xffffffffu, qacc, 1);
            qacc += __shfl_xor_sync(0xffffffffu, qacc, 2);
            if (seg4 == 0) qssf[row4] = qacc;
        }
        CPA_WAIT0();
        __syncthreads();

        const uint32_t aQH = smb + QH_O + (mrow + lrow) * KQP + lk;
        const uint32_t aQL = smb + QL_O + (mrow + lrow) * KQP + lk;
        const uint32_t bCH = smb + CH_O + (ncol + lrow) * KQP + lk;
        const uint32_t bCL = smb + CL_O + (ncol + lrow) * KQP + lk;
        #pragma unroll
        for (int ks = 0; ks < 4; ++ks) {
            uint32_t a0, a1, a2, a3, a4, a5, a6, a7;
            uint32_t e0, e1, e2, e3, u0, u1, u2, u3;
            ldsm4(aQH + ks * 32, a0, a1, a2, a3);
            ldsm4(aQH + 16 * KQP + ks * 32, a4, a5, a6, a7);
            ldsm4(bCH + ks * 32, e0, e1, e2, e3);              // CH frags, held
            MMA4(acc, a0,a1,a2,a3,a4,a5,a6,a7, e0,e1,e2,e3);   // QH x CH
            ldsm4(bCL + ks * 32, u0, u1, u2, u3);
            MMA4(acc, a0,a1,a2,a3,a4,a5,a6,a7, u0,u1,u2,u3);   // QH x CL
            ldsm4(aQL + ks * 32, a0, a1, a2, a3);
            ldsm4(aQL + 16 * KQP + ks * 32, a4, a5, a6, a7);
            MMA4(acc, a0,a1,a2,a3,a4,a5,a6,a7, e0,e1,e2,e3);   // QL x CH
        }
        __syncthreads();
    }

    // ---- store sims (full tile per warp) ----
    {
        const int r0 = mrow + (lane >> 2);
        const int cb = ncol + (lane & 3) * 2;
        #pragma unroll
        for (int mf = 0; mf < 2; ++mf)
            #pragma unroll
            for (int nf = 0; nf < 2; ++nf) {
                float* a = acc[mf * 2 + nf];
                *(float2*)(sm + S_O + (r0 + mf * 16) * SP + (cb + nf * 8) * 4) = make_float2(a[0], a[1]);
                *(float2*)(sm + S_O + (r0 + mf * 16 + 8) * SP + (cb + nf * 8) * 4) = make_float2(a[2], a[3]);
            }
    }
    __syncthreads();

    // ---- prefetch GEMM2 d-quarter 0 (CH only) into buffer 0 ----
    copy_cq(smb + C2_O, gCH, row4, seg4, 0);
    CPA_COMMIT();

    // ================= softmax + argmax: 4 threads per row =================
    {
        const int m = t >> 2, part = t & 3;
        const float qr = rsqrtf(fmaxf(qssf[m], 1e-24f));
        const float4* s0 = (const float4*)(sm + S_O + m * SP) + part * 4;
        float s[16];
        float mx = -INFINITY;
        int mi = PDIM;
        #pragma unroll
        for (int gg = 0; gg < 4; ++gg) {
            float4 v = s0[gg];
            float vv[4] = {v.x, v.y, v.z, v.w};
            #pragma unroll
            for (int i = 0; i < 4; ++i) {
                int p = part * 16 + gg * 4 + i;
                float val = fmaf(vv[i] * qr, cism[p], negm[p]);
                s[gg * 4 + i] = val;
                if (val > mx) { mx = val; mi = p; }     // strict >: first index wins
            }
        }
        #pragma unroll
        for (int off = 1; off < 4; off <<= 1) {
            float omx = __shfl_xor_sync(0xffffffffu, mx, off);
            int   omi = __shfl_xor_sync(0xffffffffu, mi, off);
            if (omx > mx || (omx == mx && omi < mi)) { mx = omx; mi = omi; }
        }
        float ssum = 0.f;
        #pragma unroll
        for (int i = 0; i < 16; ++i) {
            float e = expf(s[i] - mx);
            s[i] = e;
            ssum += e;
        }
        #pragma unroll
        for (int off = 1; off < 4; off <<= 1)
            ssum += __shfl_xor_sync(0xffffffffu, ssum, off);
        const float inv = 1.0f / ssum;

        float4* gwp = (float4*)(gw + (size_t)(mbase + m) * PDIM + part * 16);
        char* wh = sm + WH_O + m * WP + part * 32;
        #pragma unroll
        for (int gg = 0; gg < 2; ++gg) {
            float w0 = s[8 * gg + 0] * inv, w1 = s[8 * gg + 1] * inv;
            float w2 = s[8 * gg + 2] * inv, w3 = s[8 * gg + 3] * inv;
            float w4 = s[8 * gg + 4] * inv, w5 = s[8 * gg + 5] * inv;
            float w6 = s[8 * gg + 6] * inv, w7 = s[8 * gg + 7] * inv;
            gwp[2 * gg]     = make_float4(w0, w1, w2, w3);
            gwp[2 * gg + 1] = make_float4(w4, w5, w6, w7);
            uint32_t h0 = cvt2h(w1, w0), h1 = cvt2h(w3, w2);
            uint32_t h2 = cvt2h(w5, w4), h3 = cvt2h(w7, w6);
            *(uint4*)(wh + gg * 16) = make_uint4(h0, h1, h2, h3);
        }
        if (part == 0) ghard[mbase + m] = (float)mi;
    }
    __syncthreads();

    // ================= GEMM2: 4 d-quarter rounds, double-buffered, single fp16 pass =================
    {
        const int mrow2 = (wid & 1) * 32;
        const int dt = (wid >> 1) * 16;
        const uint32_t btrow = (uint32_t)((lane >> 4) * 8 + (lane & 7));
        const uint32_t btcol = (uint32_t)(((lane >> 3) & 1) * 16);
        const uint32_t aWHr = smb + WH_O + (mrow2 + lrow) * WP + lk;

        #pragma unroll 1
        for (int dq = 0; dq < 4; ++dq) {
            const uint32_t cbuf = C2_O + (uint32_t)(dq & 1) * C2STRIDE;
            if (dq < 3) {
                const uint32_t nbuf = C2_O + (uint32_t)((dq + 1) & 1) * C2STRIDE;
                copy_cq(smb + nbuf, gCH, row4, seg4, dq + 1);
                CPA_COMMIT();
                CPA_WAIT1();
            } else {
                CPA_WAIT0();
            }
            __syncthreads();

            float dd[4][4];
            #pragma unroll
            for (int i = 0; i < 4; ++i)
                #pragma unroll
                for (int j = 0; j < 4; ++j) dd[i][j] = 0.f;

            const uint32_t bC2H = smb + cbuf + btrow * KQP + dt * 2 + btcol;
            #pragma unroll
            for (int ks = 0; ks < 4; ++ks) {
                uint32_t a0, a1, a2, a3, a4, a5, a6, a7;
                uint32_t r0, r1, r2, r3;
                ldsm4(aWHr + ks * 32, a0, a1, a2, a3);
                ldsm4(aWHr + 16 * WP + ks * 32, a4, a5, a6, a7);
                ldsm4t(bC2H + ks * 16 * KQP, r0, r1, r2, r3);
                mma16816(dd[0], a0, a1, a2, a3, r0, r2);
                mma16816(dd[1], a0, a1, a2, a3, r1, r3);
                mma16816(dd[2], a4, a5, a6, a7, r0, r2);
                mma16816(dd[3], a4, a5, a6, a7, r1, r3);
            }
            const int r0l = lane >> 2;
            const int cb = dq * 64 + dt + (lane & 3) * 2;
            #pragma unroll
            for (int mf = 0; mf < 2; ++mf) {
                float* gr0 = gctx + (size_t)(mbase + mrow2 + mf * 16 + r0l) * DDIM;
                float* gr1 = gr0 + 8 * DDIM;
                #pragma unroll
                for (int nf = 0; nf < 2; ++nf) {
                    float* a = dd[mf * 2 + nf];
                    *(float2*)(gr0 + cb + nf * 8) = make_float2(a[0], a[1]);
                    *(float2*)(gr1 + cb + nf * 8) = make_float2(a[2], a[3]);
                }
            }
            __syncthreads();
        }
    }
}

extern "C" void kernel_launch(void* const* d_in, const int* in_sizes, int n_in,
                              void* d_out, int out_size)
{
    const float* q = (const float*)d_in[0];
    const float* c = (const float*)d_in[1];
    const int*   mask = (const int*)d_in[2];

    const int Pn = in_sizes[2];              // 64
    const int Dn = in_sizes[1] / Pn;         // 256
    const int B  = in_sizes[0] / Dn;         // 131072

    float* out  = (float*)d_out;
    float* ctx  = out;                           // [B, D]
    float* w    = out + (size_t)B * Dn;          // [B, P]
    float* hard = w + (size_t)B * Pn;            // [B]

    centroid_prep<<<8, 256>>>(c, mask);
    cudaFuncSetAttribute(centroid_main,
                         cudaFuncAttributeMaxDynamicSharedMemorySize, SMEM_BYTES);
    centroid_main<<<B / MTILE, NTHREADS, SMEM_BYTES>>>(q, ctx, w, hard);
}